// round 1
// baseline (speedup 1.0000x reference)
#include <cuda_runtime.h>

// Problem constants
#define Bc     4
#define Nc     6
#define CIN    256
#define Hc     16
#define Wc     44
#define Dd     59
#define COUT   64
#define HW     (Hc*Wc)            // 704
#define NPIX   (Bc*Nc*HW)         // 16896
#define XX     128
#define YY     128
#define ZZ     7
#define BEV_SIZE (Bc*COUT*YY*XX)  // 4194304

// Scratch (static device globals: no allocation)
__device__ float g_feat[NPIX * COUT];   // (B,N,H*W,64) contiguous, ~4.3MB
__device__ float g_proj[Bc*Nc*16];      // per-(b,n): e2c 3x4 rows + fx,fy,cx,cy

// ---------------------------------------------------------------------------
// Kernel 0: analytic rigid inverse of cam2ego + pack intrinsics
// ---------------------------------------------------------------------------
__global__ void proj_setup(const float* __restrict__ c2e,
                           const float* __restrict__ Kin) {
    int bn = threadIdx.x;
    if (bn >= Bc*Nc) return;
    const float* m = c2e + bn*16;
    float R[3][3], t[3];
    #pragma unroll
    for (int i = 0; i < 3; i++) {
        #pragma unroll
        for (int j = 0; j < 3; j++) R[i][j] = m[i*4+j];
        t[i] = m[i*4+3];
    }
    float* o = g_proj + bn*16;
    #pragma unroll
    for (int i = 0; i < 3; i++) {
        o[i*4+0] = R[0][i];
        o[i*4+1] = R[1][i];
        o[i*4+2] = R[2][i];
        o[i*4+3] = -(R[0][i]*t[0] + R[1][i]*t[1] + R[2][i]*t[2]);
    }
    const float* k = Kin + bn*9;
    o[12] = k[0];  // fx
    o[13] = k[4];  // fy
    o[14] = k[2];  // cx
    o[15] = k[5];  // cy
}

// ---------------------------------------------------------------------------
// Kernel 1: per-pixel GEMM (16896 x 123, K=256) + bias + softmax(59) + split
//   depth (B,N,H,W,59) -> depth_out; feat (.,64) -> g_feat
// Tile: 32 pixels x 128 outputs (123 used), K chunks of 32, 256 threads,
// thread micro-tile 4x4.
// ---------------------------------------------------------------------------
#define TM 32
#define KC 32

__global__ __launch_bounds__(256)
void gemm_softmax(const float* __restrict__ img,
                  const float* __restrict__ w,
                  const float* __restrict__ bias,
                  float* __restrict__ depth_out) {
    __shared__ float As[TM*33];       // [pix][kk] padded
    __shared__ float Ws[KC*129];      // [kk][o] padded; reused as T[32][124]
    __shared__ float pmax[TM], pinv[TM];

    const int p0  = blockIdx.x * TM;      // 704 % 32 == 0 -> tile within one (b,n)
    const int bn  = p0 / HW;
    const int hw0 = p0 - bn*HW;
    const float* abase = img + (size_t)bn*CIN*HW + hw0;

    const int tid = threadIdx.x;
    const int ox  = tid & 31;             // output lane
    const int my  = tid >> 5;             // pixel group (0..7), 4 pixels each

    float acc[4][4] = {};

    for (int kc = 0; kc < CIN; kc += KC) {
        // A tile: 32 pix x 32 k (coalesced over pix)
        #pragma unroll
        for (int r = 0; r < 4; r++) {
            int i   = tid + 256*r;
            int kk  = i >> 5;
            int pix = i & 31;
            As[pix*33 + kk] = abase[(size_t)(kc+kk)*HW + pix];
        }
        // W tile: 128 o x 32 k -> Ws[kk][o] (coalesced over k, conflict-free store)
        #pragma unroll
        for (int r = 0; r < 16; r++) {
            int i  = tid + 256*r;
            int o  = i >> 5;
            int kk = i & 31;
            Ws[kk*129 + o] = (o < 123) ? w[o*CIN + kc + kk] : 0.0f;
        }
        __syncthreads();
        #pragma unroll
        for (int kk = 0; kk < KC; kk++) {
            float a0 = As[(my*4+0)*33 + kk];
            float a1 = As[(my*4+1)*33 + kk];
            float a2 = As[(my*4+2)*33 + kk];
            float a3 = As[(my*4+3)*33 + kk];
            float b0 = Ws[kk*129 + ox];
            float b1 = Ws[kk*129 + ox + 32];
            float b2 = Ws[kk*129 + ox + 64];
            float b3 = Ws[kk*129 + ox + 96];
            acc[0][0] += a0*b0; acc[0][1] += a0*b1; acc[0][2] += a0*b2; acc[0][3] += a0*b3;
            acc[1][0] += a1*b0; acc[1][1] += a1*b1; acc[1][2] += a1*b2; acc[1][3] += a1*b3;
            acc[2][0] += a2*b0; acc[2][1] += a2*b1; acc[2][2] += a2*b2; acc[2][3] += a2*b3;
            acc[3][0] += a3*b0; acc[3][1] += a3*b1; acc[3][2] += a3*b2; acc[3][3] += a3*b3;
        }
        __syncthreads();
    }

    // Epilogue: stage logits tile [32][124] in smem (reuse Ws), add bias
    float* T = Ws;
    #pragma unroll
    for (int i = 0; i < 4; i++) {
        int m = my*4 + i;
        #pragma unroll
        for (int j = 0; j < 4; j++) {
            int o = ox + 32*j;
            if (o < 123) T[m*124 + o] = acc[i][j] + bias[o];
        }
    }
    __syncthreads();

    if (tid < TM) {
        float mx = -1e30f;
        for (int d = 0; d < Dd; d++) mx = fmaxf(mx, T[tid*124 + d]);
        float s = 0.0f;
        for (int d = 0; d < Dd; d++) s += expf(T[tid*124 + d] - mx);
        pmax[tid] = mx;
        pinv[tid] = 1.0f / s;
    }
    __syncthreads();

    // depth out: (p, d) contiguous in d
    for (int i = tid; i < TM*Dd; i += 256) {
        int pix = i / Dd;
        int d   = i - pix*Dd;
        depth_out[(size_t)(p0 + pix)*Dd + d] =
            expf(T[pix*124 + d] - pmax[pix]) * pinv[pix];
    }
    // feat scratch: (p, c) contiguous in c
    for (int i = tid; i < TM*COUT; i += 256) {
        int pix = i >> 6;
        int c   = i & 63;
        g_feat[(size_t)(p0 + pix)*COUT + c] = T[pix*124 + Dd + c];
    }
}

// ---------------------------------------------------------------------------
// Kernel 2: voxel projection + depth-weighted feature splat
// Block = (b, y): 256 threads = 8 warps. Warp w handles x in [w*16, w*16+16),
// 2 channels per lane in registers; stage in padded smem; coalesced write of
// bev[b, c, y, x].
// ---------------------------------------------------------------------------
__global__ __launch_bounds__(256)
void bev_kernel(const float* __restrict__ depth,
                float* __restrict__ bev) {
    __shared__ float sacc[XX*65];       // [x][c] padded (stride 65)
    __shared__ float scol0[Nc][3];
    __shared__ float sKc[Nc][4];
    __shared__ float sbase[Nc][ZZ][3];

    const int b = blockIdx.x >> 7;
    const int y = blockIdx.x & 127;
    const int tid = threadIdx.x;
    const float py = y*0.8f - 51.2f;

    if (tid < Nc*ZZ) {
        int n = tid / ZZ, z = tid - n*ZZ;
        const float* m = g_proj + (b*Nc + n)*16;
        float pz = (float)z - 2.5f;
        sbase[n][z][0] = py*m[1] + pz*m[2]  + m[3];
        sbase[n][z][1] = py*m[5] + pz*m[6]  + m[7];
        sbase[n][z][2] = py*m[9] + pz*m[10] + m[11];
        if (z == 0) {
            scol0[n][0] = m[0]; scol0[n][1] = m[4]; scol0[n][2] = m[8];
            sKc[n][0] = m[12]; sKc[n][1] = m[13]; sKc[n][2] = m[14]; sKc[n][3] = m[15];
        }
    }
    __syncthreads();

    const int warp = tid >> 5;
    const int lane = tid & 31;

    for (int xi = 0; xi < 16; xi++) {
        const int x = warp*16 + xi;
        const float px = x*0.8f - 51.2f;
        float a0 = 0.0f, a1 = 0.0f;

        #pragma unroll
        for (int n = 0; n < Nc; n++) {
            const float c0x = scol0[n][0], c0y = scol0[n][1], c0z = scol0[n][2];
            const float fx = sKc[n][0], fy = sKc[n][1], cx = sKc[n][2], cy = sKc[n][3];
            const int pbase = (b*Nc + n)*HW;
            #pragma unroll
            for (int z = 0; z < ZZ; z++) {
                float camx = px*c0x + sbase[n][z][0];
                float camy = px*c0y + sbase[n][z][1];
                float camz = px*c0z + sbase[n][z][2];
                float zs   = fmaxf(camz, 0.1f);
                float fu   = (fx*(camx/zs) + cx) * 0.0625f;
                float fv   = (fy*(camy/zs) + cy) * 0.0625f;
                int   db   = (int)(camz - 1.0f);   // trunc toward zero == numpy astype
                bool valid = (fu >= 0.0f) && (fu < (float)Wc) &&
                             (fv >= 0.0f) && (fv < (float)Hc) &&
                             (camz > 0.5f) && (db >= 0) && (db < Dd);
                if (!valid) continue;              // warp-uniform
                int u = (int)fu;
                int v = (int)fv;
                int hw = v*Wc + u;
                float wgt = depth[(size_t)(pbase + hw)*Dd + db];
                const float* fr = g_feat + (size_t)(pbase + hw)*COUT;
                a0 += wgt * fr[lane];
                a1 += wgt * fr[lane + 32];
            }
        }
        sacc[x*65 + lane]      = a0;
        sacc[x*65 + lane + 32] = a1;
    }
    __syncthreads();

    // bev[b, c, y, x] — coalesced over x
    for (int i = tid; i < COUT*XX; i += 256) {
        int c = i >> 7;
        int x = i & 127;
        bev[(((size_t)b*COUT + c)*YY + y)*XX + x] = sacc[x*65 + c];
    }
}

// ---------------------------------------------------------------------------
extern "C" void kernel_launch(void* const* d_in, const int* in_sizes, int n_in,
                              void* d_out, int out_size) {
    const float* img  = (const float*)d_in[0];  // (4,6,256,16,44)
    const float* c2e  = (const float*)d_in[1];  // (4,6,4,4)
    const float* Kin  = (const float*)d_in[2];  // (4,6,3,3)
    const float* w    = (const float*)d_in[3];  // (123,256)
    const float* bias = (const float*)d_in[4];  // (123,)
    float* out       = (float*)d_out;
    float* depth_out = out + BEV_SIZE;          // outputs: [bev | depth]

    proj_setup<<<1, 32>>>(c2e, Kin);
    gemm_softmax<<<NPIX/TM, 256>>>(img, w, bias, depth_out);
    bev_kernel<<<Bc*YY, 256>>>(depth_out, out);
}

// round 2
// speedup vs baseline: 3.5370x; 3.5370x over previous
#include <cuda_runtime.h>

// Problem constants
#define Bc     4
#define Nc     6
#define CIN    256
#define Hc     16
#define Wc     44
#define Dd     59
#define COUT   64
#define HW     (Hc*Wc)            // 704
#define NPIX   (Bc*Nc*HW)         // 16896
#define XX     128
#define YY     128
#define ZZ     7
#define BEV_SIZE (Bc*COUT*YY*XX)  // 4194304

// Scratch (static device globals: no allocation)
__device__ float g_feat[NPIX * COUT];   // (B,N,H*W,64) contiguous, ~4.3MB
__device__ float g_proj[Bc*Nc*16];      // per-(b,n): e2c 3x4 rows + fx,fy,cx,cy

// ---------------------------------------------------------------------------
// Kernel 0: analytic rigid inverse of cam2ego + pack intrinsics
// ---------------------------------------------------------------------------
__global__ void proj_setup(const float* __restrict__ c2e,
                           const float* __restrict__ Kin) {
    int bn = threadIdx.x;
    if (bn >= Bc*Nc) return;
    const float* m = c2e + bn*16;
    float R[3][3], t[3];
    #pragma unroll
    for (int i = 0; i < 3; i++) {
        #pragma unroll
        for (int j = 0; j < 3; j++) R[i][j] = m[i*4+j];
        t[i] = m[i*4+3];
    }
    float* o = g_proj + bn*16;
    #pragma unroll
    for (int i = 0; i < 3; i++) {
        o[i*4+0] = R[0][i];
        o[i*4+1] = R[1][i];
        o[i*4+2] = R[2][i];
        o[i*4+3] = -(R[0][i]*t[0] + R[1][i]*t[1] + R[2][i]*t[2]);
    }
    const float* k = Kin + bn*9;
    o[12] = k[0];  // fx
    o[13] = k[4];  // fy
    o[14] = k[2];  // cx
    o[15] = k[5];  // cy
}

// ---------------------------------------------------------------------------
// Kernel 1: per-pixel GEMM (16896 x 123, K=256) + bias + softmax(59) + split
// Tile: 32 pixels x 128 outputs, K chunks of 32, 256 threads, micro-tile 4x4.
// A tile [kk][pix] -> LDS.128 broadcast; W tile [kk][o] -> LDS.128 per lane.
// ---------------------------------------------------------------------------
#define TM 32
#define KC 32

__global__ __launch_bounds__(256)
void gemm_softmax(const float* __restrict__ img,
                  const float* __restrict__ w,
                  const float* __restrict__ bias,
                  float* __restrict__ depth_out) {
    __shared__ float As[KC*36];        // [kk][pix], pad 36 (row 144B, 16B-aligned)
    __shared__ float Ws[KC*132];       // [kk][o],   pad 132 (row 528B, 16B-aligned)
    __shared__ float T[TM*129];        // logits tile, stride 129 (conflict-free)
    __shared__ float pmax[TM], pinv[TM];

    const int p0  = blockIdx.x * TM;      // 704 % 32 == 0 -> tile within one (b,n)
    const int bn  = p0 / HW;
    const int hw0 = p0 - bn*HW;
    const float* abase = img + (size_t)bn*CIN*HW + hw0;

    const int tid = threadIdx.x;
    const int ox  = tid & 31;             // output group lane: o = 4*ox + j
    const int my  = tid >> 5;             // pixel group: pix = 4*my + i

    float acc[4][4] = {};

    for (int kc = 0; kc < CIN; kc += KC) {
        // A tile: [kk][pix], coalesced global read over pix
        #pragma unroll
        for (int r = 0; r < 4; r++) {
            int kk  = (tid >> 5) + 8*r;
            int pix = tid & 31;
            As[kk*36 + pix] = abase[(size_t)(kc+kk)*HW + pix];
        }
        // W tile: [kk][o], coalesced global read over kk
        #pragma unroll
        for (int r = 0; r < 16; r++) {
            int i  = tid + 256*r;
            int o  = i >> 5;
            int kk = i & 31;
            Ws[kk*132 + o] = (o < 123) ? w[o*CIN + kc + kk] : 0.0f;
        }
        __syncthreads();
        #pragma unroll
        for (int kk = 0; kk < KC; kk++) {
            float4 av = *(const float4*)&As[kk*36 + my*4];   // broadcast
            float4 bv = *(const float4*)&Ws[kk*132 + ox*4];  // conflict-free
            acc[0][0] += av.x*bv.x; acc[0][1] += av.x*bv.y; acc[0][2] += av.x*bv.z; acc[0][3] += av.x*bv.w;
            acc[1][0] += av.y*bv.x; acc[1][1] += av.y*bv.y; acc[1][2] += av.y*bv.z; acc[1][3] += av.y*bv.w;
            acc[2][0] += av.z*bv.x; acc[2][1] += av.z*bv.y; acc[2][2] += av.z*bv.z; acc[2][3] += av.z*bv.w;
            acc[3][0] += av.w*bv.x; acc[3][1] += av.w*bv.y; acc[3][2] += av.w*bv.z; acc[3][3] += av.w*bv.w;
        }
        __syncthreads();
    }

    // Epilogue: stage logits tile [32][129] in smem, add bias
    #pragma unroll
    for (int i = 0; i < 4; i++) {
        int m = my*4 + i;
        #pragma unroll
        for (int j = 0; j < 4; j++) {
            int o = ox*4 + j;
            if (o < 123) T[m*129 + o] = acc[i][j] + bias[o];
        }
    }
    __syncthreads();

    // Warp-parallel softmax stats: warp handles 4 pixels
    {
        int warp = tid >> 5, lane = tid & 31;
        #pragma unroll
        for (int i = 0; i < 4; i++) {
            int p = warp*4 + i;
            float v0 = (lane      < Dd) ? T[p*129 + lane]      : -3.4e38f;
            float v1 = (lane + 32 < Dd) ? T[p*129 + lane + 32] : -3.4e38f;
            float mx = fmaxf(v0, v1);
            #pragma unroll
            for (int o = 16; o; o >>= 1) mx = fmaxf(mx, __shfl_xor_sync(~0u, mx, o));
            float s = 0.0f;
            if (lane      < Dd) s += expf(v0 - mx);
            if (lane + 32 < Dd) s += expf(v1 - mx);
            #pragma unroll
            for (int o = 16; o; o >>= 1) s += __shfl_xor_sync(~0u, s, o);
            if (lane == 0) { pmax[p] = mx; pinv[p] = 1.0f / s; }
        }
    }
    __syncthreads();

    // depth out: (p, d) contiguous in d
    for (int i = tid; i < TM*Dd; i += 256) {
        int pix = i / Dd;
        int d   = i - pix*Dd;
        depth_out[(size_t)(p0 + pix)*Dd + d] =
            expf(T[pix*129 + d] - pmax[pix]) * pinv[pix];
    }
    // feat scratch: (p, c) contiguous in c
    for (int i = tid; i < TM*COUT; i += 256) {
        int pix = i >> 6;
        int c   = i & 63;
        g_feat[(size_t)(p0 + pix)*COUT + c] = T[pix*129 + Dd + c];
    }
}

// ---------------------------------------------------------------------------
// Kernel 2: voxel projection + depth-weighted feature splat, two-phase.
// Block = (b, y, x-half): 1024 blocks x 256 threads.
//  Phase A: one projection per lane (2688/block), depth weight gathered with
//           predicated per-lane LDG (MLP ~32), result -> fixed smem slot
//           (wgt=0 if invalid) -> deterministic.
//  Phase B: warp owns 8 x values; fixed 42-trip loop, 8B smem broadcast per
//           entry, feat gather in a short predicated arm (no traffic when
//           warp-uniformly invalid, loads batch across unrolled iters).
// ---------------------------------------------------------------------------
#define XH 64   // x values per block

__global__ __launch_bounds__(256)
void bev_kernel(const float* __restrict__ depth,
                float* __restrict__ bev) {
    __shared__ float2 sl[XH*42];        // [x][s] (wgt, feat_off_as_float): 21504B
    __shared__ float  sacc[XH*65];      // [x][c] padded: 16640B
    __shared__ float  sbase[Nc][ZZ][3];
    __shared__ float  scol0[Nc][4];
    __shared__ float  sK[Nc][4];

    const int blk = blockIdx.x;
    const int xh  = blk & 1;
    const int y   = (blk >> 1) & 127;
    const int b   = blk >> 8;
    const int tid = threadIdx.x;
    const float py = y*0.8f - 51.2f;

    if (tid < Nc*ZZ) {
        int n = tid / ZZ, z = tid - n*ZZ;
        const float* m = g_proj + (b*Nc + n)*16;
        float pz = (float)z - 2.5f;
        sbase[n][z][0] = py*m[1] + pz*m[2]  + m[3];
        sbase[n][z][1] = py*m[5] + pz*m[6]  + m[7];
        sbase[n][z][2] = py*m[9] + pz*m[10] + m[11];
        if (z == 0) {
            scol0[n][0] = m[0]; scol0[n][1] = m[4]; scol0[n][2] = m[8];
            sK[n][0] = m[12]; sK[n][1] = m[13]; sK[n][2] = m[14]; sK[n][3] = m[15];
        }
    }
    __syncthreads();

    // ---- Phase A: per-lane projections ----
    #pragma unroll
    for (int r = 0; r < 11; r++) {
        int idx = tid + 256*r;
        if (idx < Nc*ZZ*XH) {
            int x = idx & (XH-1);
            int s = idx >> 6;          // 0..41 (warp-uniform)
            int n = s / ZZ;
            int z = s - n*ZZ;
            float px = (float)(xh*XH + x)*0.8f - 51.2f;
            float camx = px*scol0[n][0] + sbase[n][z][0];
            float camy = px*scol0[n][1] + sbase[n][z][1];
            float camz = px*scol0[n][2] + sbase[n][z][2];
            float zs   = fmaxf(camz, 0.1f);
            float fu   = (sK[n][0]*(camx/zs) + sK[n][2]) * 0.0625f;
            float fv   = (sK[n][1]*(camy/zs) + sK[n][3]) * 0.0625f;
            int   db   = (int)(camz - 1.0f);   // trunc == numpy astype(int32)
            bool valid = (fu >= 0.0f) && (fu < (float)Wc) &&
                         (fv >= 0.0f) && (fv < (float)Hc) &&
                         (camz > 0.5f) && (db >= 0) && (db < Dd);
            float wgt = 0.0f;
            int   off = 0;
            if (valid) {
                int u = (int)fu;
                int v = (int)fv;
                int p = (b*Nc + n)*HW + v*Wc + u;
                wgt = depth[(size_t)p*Dd + db];
                off = p*COUT;
            }
            sl[x*42 + s] = make_float2(wgt, __int_as_float(off));
        }
    }
    __syncthreads();

    // ---- Phase B: warp-per-8x accumulation ----
    const int warp = tid >> 5;
    const int lane = tid & 31;

    for (int xi = 0; xi < 8; xi++) {
        const int x = warp*8 + xi;
        float a0 = 0.0f, a1 = 0.0f;
        #pragma unroll 14
        for (int j = 0; j < Nc*ZZ; j++) {
            float2 e = sl[x*42 + j];           // 8B broadcast
            int off = __float_as_int(e.y);
            if (e.x != 0.0f) {                 // warp-uniform -> predicated arm
                a0 = fmaf(e.x, g_feat[off + lane],      a0);
                a1 = fmaf(e.x, g_feat[off + lane + 32], a1);
            }
        }
        sacc[x*65 + lane]      = a0;
        sacc[x*65 + lane + 32] = a1;
    }
    __syncthreads();

    // bev[b, c, y, x] — coalesced over x (64-wide segments)
    for (int i = tid; i < COUT*XH; i += 256) {
        int c = i >> 6;
        int x = i & 63;
        bev[(((size_t)b*COUT + c)*YY + y)*XX + xh*XH + x] = sacc[x*65 + c];
    }
}

// ---------------------------------------------------------------------------
extern "C" void kernel_launch(void* const* d_in, const int* in_sizes, int n_in,
                              void* d_out, int out_size) {
    const float* img  = (const float*)d_in[0];  // (4,6,256,16,44)
    const float* c2e  = (const float*)d_in[1];  // (4,6,4,4)
    const float* Kin  = (const float*)d_in[2];  // (4,6,3,3)
    const float* w    = (const float*)d_in[3];  // (123,256)
    const float* bias = (const float*)d_in[4];  // (123,)
    float* out       = (float*)d_out;
    float* depth_out = out + BEV_SIZE;          // outputs: [bev | depth]

    proj_setup<<<1, 32>>>(c2e, Kin);
    gemm_softmax<<<NPIX/TM, 256>>>(img, w, bias, depth_out);
    bev_kernel<<<Bc*YY*2, 256>>>(depth_out, out);
}

// round 3
// speedup vs baseline: 3.9119x; 1.1060x over previous
#include <cuda_runtime.h>
#include <cstdint>

// Problem constants
#define Bc     4
#define Nc     6
#define CIN    256
#define Hc     16
#define Wc     44
#define Dd     59
#define COUT   64
#define HW     (Hc*Wc)            // 704
#define NPIX   (Bc*Nc*HW)         // 16896
#define XX     128
#define YY     128
#define ZZ     7
#define BEV_SIZE (Bc*COUT*YY*XX)  // 4194304

// Scratch (static device global: no allocation)
__device__ float g_feat[NPIX * COUT];   // (B,N,H*W,64) contiguous, ~4.3MB

// packed fp32x2 helpers (sm_103a FFMA2 — only reachable via PTX)
#define PACK2(d, lo, hi)  asm("mov.b64 %0, {%1, %2};" : "=l"(d) : "f"(lo), "f"(hi))
#define PACK2S(d, v)      asm("mov.b64 %0, {%1, %1};" : "=l"(d) : "f"(v))
#define UNPACK2(lo, hi, s) asm("mov.b64 {%0, %1}, %2;" : "=f"(lo), "=f"(hi) : "l"(s))
#define FFMA2(acc, a, b)  asm("fma.rn.f32x2 %0, %1, %2, %0;" : "+l"(acc) : "l"(a), "l"(b))

// ---------------------------------------------------------------------------
// Kernel 1: per-pixel GEMM (16896 x 123, K=256) + bias + softmax(59) + split
// Tile: 32 pixels x 128 outputs, K chunks of 32, 256 threads, micro-tile 4x4,
// accumulators packed as f32x2 pairs -> FFMA2 (2 lane-FMA per issue).
// ---------------------------------------------------------------------------
#define TM 32
#define KC 32

__global__ __launch_bounds__(256)
void gemm_softmax(const float* __restrict__ img,
                  const float* __restrict__ w,
                  const float* __restrict__ bias,
                  float* __restrict__ depth_out) {
    __shared__ float As[KC*36];        // [kk][pix]
    __shared__ float Ws[KC*132];       // [kk][o]
    __shared__ float T[TM*129];        // logits tile
    __shared__ float pmax[TM], pinv[TM];

    const int p0  = blockIdx.x * TM;      // 704 % 32 == 0 -> tile within one (b,n)
    const int bn  = p0 / HW;
    const int hw0 = p0 - bn*HW;
    const float* abase = img + (size_t)bn*CIN*HW + hw0;

    const int tid = threadIdx.x;
    const int ox  = tid & 31;             // output group: o = 4*ox + j
    const int my  = tid >> 5;             // pixel group:  pix = 4*my + i

    uint64_t acc01[4] = {0,0,0,0};        // {o+0,o+1} per pixel
    uint64_t acc23[4] = {0,0,0,0};        // {o+2,o+3} per pixel

    for (int kc = 0; kc < CIN; kc += KC) {
        #pragma unroll
        for (int r = 0; r < 4; r++) {
            int kk  = (tid >> 5) + 8*r;
            int pix = tid & 31;
            As[kk*36 + pix] = abase[(size_t)(kc+kk)*HW + pix];
        }
        #pragma unroll
        for (int r = 0; r < 16; r++) {
            int i  = tid + 256*r;
            int o  = i >> 5;
            int kk = i & 31;
            Ws[kk*132 + o] = (o < 123) ? w[o*CIN + kc + kk] : 0.0f;
        }
        __syncthreads();
        #pragma unroll
        for (int kk = 0; kk < KC; kk++) {
            float4 av = *(const float4*)&As[kk*36 + my*4];   // broadcast
            float4 bv = *(const float4*)&Ws[kk*132 + ox*4];  // conflict-free
            uint64_t b01, b23;
            PACK2(b01, bv.x, bv.y);
            PACK2(b23, bv.z, bv.w);
            float a_[4] = {av.x, av.y, av.z, av.w};
            #pragma unroll
            for (int i = 0; i < 4; i++) {
                uint64_t pa;
                PACK2S(pa, a_[i]);
                FFMA2(acc01[i], pa, b01);
                FFMA2(acc23[i], pa, b23);
            }
        }
        __syncthreads();
    }

    // Epilogue: stage logits tile in smem, add bias
    #pragma unroll
    for (int i = 0; i < 4; i++) {
        int m = my*4 + i;
        float o0, o1, o2, o3;
        UNPACK2(o0, o1, acc01[i]);
        UNPACK2(o2, o3, acc23[i]);
        int ob = ox*4;
        float r_[4] = {o0, o1, o2, o3};
        #pragma unroll
        for (int j = 0; j < 4; j++) {
            int o = ob + j;
            if (o < 123) T[m*129 + o] = r_[j] + bias[o];
        }
    }
    __syncthreads();

    // Warp-parallel softmax stats: warp handles 4 pixels
    {
        int warp = tid >> 5, lane = tid & 31;
        #pragma unroll
        for (int i = 0; i < 4; i++) {
            int p = warp*4 + i;
            float v0 = (lane      < Dd) ? T[p*129 + lane]      : -3.4e38f;
            float v1 = (lane + 32 < Dd) ? T[p*129 + lane + 32] : -3.4e38f;
            float mx = fmaxf(v0, v1);
            #pragma unroll
            for (int o = 16; o; o >>= 1) mx = fmaxf(mx, __shfl_xor_sync(~0u, mx, o));
            float s = 0.0f;
            if (lane      < Dd) s += expf(v0 - mx);
            if (lane + 32 < Dd) s += expf(v1 - mx);
            #pragma unroll
            for (int o = 16; o; o >>= 1) s += __shfl_xor_sync(~0u, s, o);
            if (lane == 0) { pmax[p] = mx; pinv[p] = 1.0f / s; }
        }
    }
    __syncthreads();

    for (int i = tid; i < TM*Dd; i += 256) {
        int pix = i / Dd;
        int d   = i - pix*Dd;
        depth_out[(size_t)(p0 + pix)*Dd + d] =
            expf(T[pix*129 + d] - pmax[pix]) * pinv[pix];
    }
    for (int i = tid; i < TM*COUT; i += 256) {
        int pix = i >> 6;
        int c   = i & 63;
        g_feat[(size_t)(p0 + pix)*COUT + c] = T[pix*129 + Dd + c];
    }
}

// ---------------------------------------------------------------------------
// Kernel 2: voxel projection + depth-weighted feature splat, two-phase.
// proj inverse folded into setup (each of 42 setup threads computes its rows).
// Phase B: lane owns channel pair (2l, 2l+1) -> LDG.64 + FFMA2 per entry.
// ---------------------------------------------------------------------------
#define XH 64   // x values per block

__global__ __launch_bounds__(256)
void bev_kernel(const float* __restrict__ c2e,
                const float* __restrict__ Kin,
                const float* __restrict__ depth,
                float* __restrict__ bev) {
    __shared__ float2 sl[XH*42];        // [x][s] (wgt, feat_off_as_float)
    __shared__ float  sacc[XH*65];      // [x][c] padded
    __shared__ float  sbase[Nc][ZZ][3];
    __shared__ float  scol0[Nc][4];
    __shared__ float  sK[Nc][4];

    const int blk = blockIdx.x;
    const int xh  = blk & 1;
    const int y   = (blk >> 1) & 127;
    const int b   = blk >> 8;
    const int tid = threadIdx.x;
    const float py = y*0.8f - 51.2f;

    if (tid < Nc*ZZ) {
        int n = tid / ZZ, z = tid - n*ZZ;
        const float* m = c2e + (b*Nc + n)*16;   // cam2ego 4x4
        float pz = (float)z - 2.5f;
        // e2c[i][j] = R[j][i] = m[j*4+i];  e2c[i][3] = -sum_j R[j][i]*t[j]
        #pragma unroll
        for (int i = 0; i < 3; i++) {
            float e1 = m[4+i], e2 = m[8+i];
            float e3 = -(m[i]*m[3] + e1*m[7] + e2*m[11]);
            sbase[n][z][i] = py*e1 + pz*e2 + e3;
        }
        if (z == 0) {
            scol0[n][0] = m[0]; scol0[n][1] = m[1]; scol0[n][2] = m[2];
            const float* k = Kin + (b*Nc + n)*9;
            sK[n][0] = k[0]; sK[n][1] = k[4]; sK[n][2] = k[2]; sK[n][3] = k[5];
        }
    }
    __syncthreads();

    // ---- Phase A: per-lane projections ----
    #pragma unroll
    for (int r = 0; r < 11; r++) {
        int idx = tid + 256*r;
        if (idx < Nc*ZZ*XH) {
            int x = idx & (XH-1);
            int s = idx >> 6;          // 0..41
            int n = s / ZZ;
            int z = s - n*ZZ;
            float px = (float)(xh*XH + x)*0.8f - 51.2f;
            float camx = px*scol0[n][0] + sbase[n][z][0];
            float camy = px*scol0[n][1] + sbase[n][z][1];
            float camz = px*scol0[n][2] + sbase[n][z][2];
            float zs   = fmaxf(camz, 0.1f);
            float fu   = (sK[n][0]*(camx/zs) + sK[n][2]) * 0.0625f;
            float fv   = (sK[n][1]*(camy/zs) + sK[n][3]) * 0.0625f;
            int   db   = (int)(camz - 1.0f);   // trunc == numpy astype(int32)
            bool valid = (fu >= 0.0f) && (fu < (float)Wc) &&
                         (fv >= 0.0f) && (fv < (float)Hc) &&
                         (camz > 0.5f) && (db >= 0) && (db < Dd);
            float wgt = 0.0f;
            int   off = 0;
            if (valid) {
                int u = (int)fu;
                int v = (int)fv;
                int p = (b*Nc + n)*HW + v*Wc + u;
                wgt = depth[(size_t)p*Dd + db];
                off = p*COUT;
            }
            sl[x*42 + s] = make_float2(wgt, __int_as_float(off));
        }
    }
    __syncthreads();

    // ---- Phase B: warp-per-8x accumulation, channel pair per lane ----
    const int warp = tid >> 5;
    const int lane = tid & 31;

    for (int xi = 0; xi < 8; xi++) {
        const int x = warp*8 + xi;
        uint64_t acc = 0;                       // packed {c=2l, c=2l+1}
        #pragma unroll 14
        for (int j = 0; j < Nc*ZZ; j++) {
            float2 e = sl[x*42 + j];            // 8B broadcast
            int off = __float_as_int(e.y);
            if (e.x != 0.0f) {                  // warp-uniform -> predicated arm
                float2 f = ((const float2*)(g_feat + off))[lane];
                uint64_t pw, fv;
                PACK2S(pw, e.x);
                PACK2(fv, f.x, f.y);
                FFMA2(acc, pw, fv);
            }
        }
        float a0, a1;
        UNPACK2(a0, a1, acc);
        sacc[x*65 + 2*lane]     = a0;
        sacc[x*65 + 2*lane + 1] = a1;
    }
    __syncthreads();

    // bev[b, c, y, x] — coalesced over x (64-wide segments)
    for (int i = tid; i < COUT*XH; i += 256) {
        int c = i >> 6;
        int x = i & 63;
        bev[(((size_t)b*COUT + c)*YY + y)*XX + xh*XH + x] = sacc[x*65 + c];
    }
}

// ---------------------------------------------------------------------------
extern "C" void kernel_launch(void* const* d_in, const int* in_sizes, int n_in,
                              void* d_out, int out_size) {
    const float* img  = (const float*)d_in[0];  // (4,6,256,16,44)
    const float* c2e  = (const float*)d_in[1];  // (4,6,4,4)
    const float* Kin  = (const float*)d_in[2];  // (4,6,3,3)
    const float* w    = (const float*)d_in[3];  // (123,256)
    const float* bias = (const float*)d_in[4];  // (123,)
    float* out       = (float*)d_out;
    float* depth_out = out + BEV_SIZE;          // outputs: [bev | depth]

    gemm_softmax<<<NPIX/TM, 256>>>(img, w, bias, depth_out);
    bev_kernel<<<Bc*YY*2, 256>>>(c2e, Kin, depth_out, out);
}

// round 4
// speedup vs baseline: 4.0004x; 1.0226x over previous
#include <cuda_runtime.h>
#include <cstdint>

// Problem constants
#define Bc     4
#define Nc     6
#define CIN    256
#define Hc     16
#define Wc     44
#define Dd     59
#define COUT   64
#define HW     (Hc*Wc)            // 704
#define NPIX   (Bc*Nc*HW)         // 16896
#define XX     128
#define YY     128
#define ZZ     7
#define BEV_SIZE (Bc*COUT*YY*XX)  // 4194304

// Scratch (static device global: no allocation)
__device__ float g_feat[NPIX * COUT];   // (B,N,H*W,64) contiguous, ~4.3MB

// packed fp32x2 helpers (sm_103a FFMA2 — only reachable via PTX)
#define PACK2S(d, v)       asm("mov.b64 %0, {%1, %1};" : "=l"(d) : "f"(v))
#define UNPACK2(lo, hi, s) asm("mov.b64 {%0, %1}, %2;" : "=f"(lo), "=f"(hi) : "l"(s))
#define FFMA2(acc, a, b)   asm("fma.rn.f32x2 %0, %1, %2, %0;" : "+l"(acc) : "l"(a), "l"(b))

// ---------------------------------------------------------------------------
// Kernel 1: per-pixel GEMM (16896 x 123, K=256) + bias + softmax(59) + split
// Tile: 64 pixels x 128 outputs, K chunks of 32, 256 threads.
// Micro-tile 4 pix x 8 out. A stored duplicated ({a,a} pairs) so the inner
// loop is 4x LDS.128 + 16x FFMA2 with zero pack movs.
// ---------------------------------------------------------------------------
#define TM 64
#define KC 32
#define ROWP 132   // padded row (floats), 528B, 16B-aligned

__global__ __launch_bounds__(256)
void gemm_softmax(const float* __restrict__ img,
                  const float* __restrict__ w,
                  const float* __restrict__ bias,
                  float* __restrict__ depth_out) {
    __shared__ float pool[2*KC*ROWP];   // As2 | Ws; reused as T[64*129] after loop
    __shared__ float pmax[TM], pinv[TM];
    float* As2 = pool;                  // [kk][2*pix] (duplicated pairs)
    float* Ws  = pool + KC*ROWP;        // [kk][o]
    float* T   = pool;                  // logits tile [pix][129] (aliases)

    const int p0  = blockIdx.x * TM;      // 704 % 64 == 0 -> tile within one (b,n)
    const int bn  = p0 / HW;
    const int hw0 = p0 - bn*HW;
    const float* abase = img + (size_t)bn*CIN*HW + hw0;

    const int tid = threadIdx.x;
    const int ox  = tid & 15;             // outputs ox*8 .. ox*8+7
    const int my  = tid >> 4;             // pixels  my*4 .. my*4+3

    uint64_t acc[4][4] = {};              // [pix][out-pair]

    for (int kc = 0; kc < CIN; kc += KC) {
        // A tile: 64 pix x 32 kk, duplicated store (STS.64 of {v,v})
        #pragma unroll
        for (int r = 0; r < 8; r++) {
            int i   = tid + 256*r;
            int kk  = i >> 6;
            int pix = i & 63;
            float v = abase[(size_t)(kc+kk)*HW + pix];
            *(float2*)&As2[kk*ROWP + 2*pix] = make_float2(v, v);
        }
        // W tile: [kk][o], coalesced over kk
        #pragma unroll
        for (int r = 0; r < 16; r++) {
            int i  = tid + 256*r;
            int o  = i >> 5;
            int kk = i & 31;
            Ws[kk*ROWP + o] = (o < 123) ? w[o*CIN + kc + kk] : 0.0f;
        }
        __syncthreads();
        #pragma unroll
        for (int kk = 0; kk < KC; kk++) {
            ulonglong2 a01 = *(const ulonglong2*)&As2[kk*ROWP + my*8];
            ulonglong2 a23 = *(const ulonglong2*)&As2[kk*ROWP + my*8 + 4];
            ulonglong2 b03 = *(const ulonglong2*)&Ws[kk*ROWP + ox*8];
            ulonglong2 b47 = *(const ulonglong2*)&Ws[kk*ROWP + ox*8 + 4];
            uint64_t a_[4] = {a01.x, a01.y, a23.x, a23.y};
            uint64_t b_[4] = {b03.x, b03.y, b47.x, b47.y};
            #pragma unroll
            for (int i = 0; i < 4; i++) {
                #pragma unroll
                for (int q = 0; q < 4; q++) FFMA2(acc[i][q], a_[i], b_[q]);
            }
        }
        __syncthreads();
    }

    // Epilogue: stage logits tile [64][129] (aliases pool), add bias
    #pragma unroll
    for (int i = 0; i < 4; i++) {
        int m = my*4 + i;
        float v[8];
        #pragma unroll
        for (int q = 0; q < 4; q++) UNPACK2(v[2*q], v[2*q+1], acc[i][q]);
        #pragma unroll
        for (int q = 0; q < 8; q++) {
            int o = ox*8 + q;
            if (o < 123) T[m*129 + o] = v[q] + bias[o];
        }
    }
    __syncthreads();

    // Warp-parallel softmax stats: warp handles 8 pixels
    {
        int warp = tid >> 5, lane = tid & 31;
        #pragma unroll
        for (int i = 0; i < 8; i++) {
            int p = warp*8 + i;
            float v0 = (lane      < Dd) ? T[p*129 + lane]      : -3.4e38f;
            float v1 = (lane + 32 < Dd) ? T[p*129 + lane + 32] : -3.4e38f;
            float mx = fmaxf(v0, v1);
            #pragma unroll
            for (int o = 16; o; o >>= 1) mx = fmaxf(mx, __shfl_xor_sync(~0u, mx, o));
            float s = 0.0f;
            if (lane      < Dd) s += expf(v0 - mx);
            if (lane + 32 < Dd) s += expf(v1 - mx);
            #pragma unroll
            for (int o = 16; o; o >>= 1) s += __shfl_xor_sync(~0u, s, o);
            if (lane == 0) { pmax[p] = mx; pinv[p] = 1.0f / s; }
        }
    }
    __syncthreads();

    for (int i = tid; i < TM*Dd; i += 256) {
        int pix = i / Dd;
        int d   = i - pix*Dd;
        depth_out[(size_t)(p0 + pix)*Dd + d] =
            expf(T[pix*129 + d] - pmax[pix]) * pinv[pix];
    }
    for (int i = tid; i < TM*COUT; i += 256) {
        int pix = i >> 6;
        int c   = i & 63;
        g_feat[(size_t)(p0 + pix)*COUT + c] = T[pix*129 + Dd + c];
    }
}

// ---------------------------------------------------------------------------
// Kernel 2: voxel projection + depth-weighted feature splat, two-phase.
// Block = (b, y, x-quarter of 32). Grid 2048 x 256 thr, ~20KB smem.
//  Phase A: one projection per lane, depth weight via predicated LDG,
//           (wgt, feat_off) -> fixed smem slot (deterministic).
//  Phase B: half-warp per x (2 x per warp), lane owns 4 channels via
//           LDG.128 -> direct ulonglong2 operands -> 2x FFMA2 per entry.
// ---------------------------------------------------------------------------
#define XQ 32   // x values per block
#define SACCP 68  // sacc row stride (floats), 272B, 16B-aligned

__global__ __launch_bounds__(256)
void bev_kernel(const float* __restrict__ c2e,
                const float* __restrict__ Kin,
                const float* __restrict__ depth,
                float* __restrict__ bev) {
    __shared__ float2 sl[XQ*42];        // [x][s] (wgt, feat_off_as_float): 10.75KB
    __shared__ float  sacc[XQ*SACCP];   // [x][c]: 8.7KB
    __shared__ float  sbase[Nc][ZZ][3];
    __shared__ float  scol0[Nc][4];
    __shared__ float  sK[Nc][4];

    const int blk = blockIdx.x;
    const int xq  = blk & 3;
    const int y   = (blk >> 2) & 127;
    const int b   = blk >> 9;
    const int tid = threadIdx.x;
    const float py = y*0.8f - 51.2f;

    if (tid < Nc*ZZ) {
        int n = tid / ZZ, z = tid - n*ZZ;
        const float* m = c2e + (b*Nc + n)*16;   // cam2ego 4x4
        float pz = (float)z - 2.5f;
        // e2c[i][j] = R[j][i];  e2c[i][3] = -sum_j R[j][i]*t[j]
        #pragma unroll
        for (int i = 0; i < 3; i++) {
            float e1 = m[4+i], e2 = m[8+i];
            float e3 = -(m[i]*m[3] + e1*m[7] + e2*m[11]);
            sbase[n][z][i] = py*e1 + pz*e2 + e3;
        }
        if (z == 0) {
            scol0[n][0] = m[0]; scol0[n][1] = m[1]; scol0[n][2] = m[2];
            const float* k = Kin + (b*Nc + n)*9;
            sK[n][0] = k[0]; sK[n][1] = k[4]; sK[n][2] = k[2]; sK[n][3] = k[5];
        }
    }
    __syncthreads();

    // ---- Phase A: per-lane projections (42 samples x 32 x = 1344) ----
    #pragma unroll
    for (int r = 0; r < 6; r++) {
        int idx = tid + 256*r;
        if (idx < Nc*ZZ*XQ) {
            int x = idx & (XQ-1);
            int s = idx >> 5;          // 0..41 (warp-uniform)
            int n = s / ZZ;
            int z = s - n*ZZ;
            float px = (float)(xq*XQ + x)*0.8f - 51.2f;
            float camx = px*scol0[n][0] + sbase[n][z][0];
            float camy = px*scol0[n][1] + sbase[n][z][1];
            float camz = px*scol0[n][2] + sbase[n][z][2];
            float zs   = fmaxf(camz, 0.1f);
            float fu   = (sK[n][0]*(camx/zs) + sK[n][2]) * 0.0625f;
            float fv   = (sK[n][1]*(camy/zs) + sK[n][3]) * 0.0625f;
            int   db   = (int)(camz - 1.0f);   // trunc == numpy astype(int32)
            bool valid = (fu >= 0.0f) && (fu < (float)Wc) &&
                         (fv >= 0.0f) && (fv < (float)Hc) &&
                         (camz > 0.5f) && (db >= 0) && (db < Dd);
            float wgt = 0.0f;
            int   off = 0;
            if (valid) {
                int u = (int)fu;
                int v = (int)fv;
                int p = (b*Nc + n)*HW + v*Wc + u;
                wgt = depth[(size_t)p*Dd + db];
                off = p*COUT;
            }
            sl[x*42 + s] = make_float2(wgt, __int_as_float(off));
        }
    }
    __syncthreads();

    // ---- Phase B: half-warp per x, 4 channels per lane ----
    const int warp = tid >> 5;
    const int lane = tid & 31;
    const int xi   = lane >> 4;        // which x of the pair
    const int cl   = lane & 15;        // channel group: c = 4*cl .. 4*cl+3

    #pragma unroll
    for (int it = 0; it < 2; it++) {
        const int x = warp*4 + it*2 + xi;
        uint64_t acc0 = 0, acc1 = 0;   // packed {4cl,4cl+1}, {4cl+2,4cl+3}
        #pragma unroll 14
        for (int j = 0; j < Nc*ZZ; j++) {
            float2 e = sl[x*42 + j];               // 8B, 2 addrs per warp
            if (e.x != 0.0f) {                     // per-half-warp predicate
                int off = __float_as_int(e.y);
                ulonglong2 fv = *(const ulonglong2*)(g_feat + off + cl*4);
                uint64_t pw;
                PACK2S(pw, e.x);
                FFMA2(acc0, pw, fv.x);
                FFMA2(acc1, pw, fv.y);
            }
        }
        float c0, c1, c2, c3;
        UNPACK2(c0, c1, acc0);
        UNPACK2(c2, c3, acc1);
        *(float4*)&sacc[x*SACCP + cl*4] = make_float4(c0, c1, c2, c3);
    }
    __syncthreads();

    // bev[b, c, y, x] — 32-wide contiguous segments
    #pragma unroll
    for (int r = 0; r < 8; r++) {
        int i = tid + 256*r;
        int c = i >> 5;
        int x = i & 31;
        bev[(((size_t)b*COUT + c)*YY + y)*XX + xq*XQ + x] = sacc[x*SACCP + c];
    }
}

// ---------------------------------------------------------------------------
extern "C" void kernel_launch(void* const* d_in, const int* in_sizes, int n_in,
                              void* d_out, int out_size) {
    const float* img  = (const float*)d_in[0];  // (4,6,256,16,44)
    const float* c2e  = (const float*)d_in[1];  // (4,6,4,4)
    const float* Kin  = (const float*)d_in[2];  // (4,6,3,3)
    const float* w    = (const float*)d_in[3];  // (123,256)
    const float* bias = (const float*)d_in[4];  // (123,)
    float* out       = (float*)d_out;
    float* depth_out = out + BEV_SIZE;          // outputs: [bev | depth]

    gemm_softmax<<<NPIX/TM, 256>>>(img, w, bias, depth_out);
    bev_kernel<<<Bc*YY*4, 256>>>(c2e, Kin, depth_out, out);
}

// round 5
// speedup vs baseline: 5.0576x; 1.2643x over previous
#include <cuda_runtime.h>
#include <cstdint>

// Problem constants
#define Bc     4
#define Nc     6
#define CIN    256
#define Hc     16
#define Wc     44
#define Dd     59
#define COUT   64
#define HW     (Hc*Wc)            // 704
#define NPIX   (Bc*Nc*HW)         // 16896
#define XX     128
#define YY     128
#define ZZ     7
#define BEV_SIZE (Bc*COUT*YY*XX)  // 4194304

// Scratch (static device global: no allocation)
__device__ float g_feat[NPIX * COUT];   // (B,N,H*W,64) contiguous, ~4.3MB

// packed fp32x2 helpers (sm_103a FFMA2 — only reachable via PTX)
#define PACK2S(d, v)       asm("mov.b64 %0, {%1, %1};" : "=l"(d) : "f"(v))
#define UNPACK2(lo, hi, s) asm("mov.b64 {%0, %1}, %2;" : "=f"(lo), "=f"(hi) : "l"(s))
#define FFMA2(acc, a, b)   asm("fma.rn.f32x2 %0, %1, %2, %0;" : "+l"(acc) : "l"(a), "l"(b))

// ---------------------------------------------------------------------------
// Kernel 1: per-pixel GEMM (16896 x 123, K=256) + bias + softmax(59) + split
// Tile: 64 pixels x 128 outputs, 128 threads, micro-tile 8 pix x 8 out.
// A stored duplicated ({a,a} pairs): inner loop = 6 LDS.128 + 32 FFMA2 per kk.
// ---------------------------------------------------------------------------
#define TM 64
#define KC 32
#define ROWP 132   // padded row (floats): fits 128 dup-A / 128 W outputs

__global__ __launch_bounds__(128)
void gemm_softmax(const float* __restrict__ img,
                  const float* __restrict__ w,
                  const float* __restrict__ bias,
                  float* __restrict__ depth_out) {
    __shared__ float pool[2*KC*ROWP];   // As2 | Ws; reused as T[64*129] after loop
    __shared__ float pmax[TM], pinv[TM];
    float* As2 = pool;                  // [kk][2*pix] (duplicated pairs)
    float* Ws  = pool + KC*ROWP;        // [kk][o]
    float* T   = pool;                  // logits tile [pix][129] (aliases)

    const int p0  = blockIdx.x * TM;      // 704 % 64 == 0 -> tile within one (b,n)
    const int bn  = p0 / HW;
    const int hw0 = p0 - bn*HW;
    const float* abase = img + (size_t)bn*CIN*HW + hw0;

    const int tid = threadIdx.x;
    const int ox  = tid & 15;             // outputs ox*8 .. ox*8+7
    const int my  = tid >> 4;             // pixels  my*8 .. my*8+7

    uint64_t acc[8][4] = {};              // [pix][out-pair]

    for (int kc = 0; kc < CIN; kc += KC) {
        // A tile: 64 pix x 32 kk, LDG.64 + duplicated STS
        #pragma unroll
        for (int r = 0; r < 8; r++) {
            int i   = tid + 128*r;
            int kk  = i >> 5;
            int px2 = (i & 31) * 2;
            float2 v = *(const float2*)&abase[(size_t)(kc+kk)*HW + px2];
            *(float2*)&As2[kk*ROWP + 2*px2]     = make_float2(v.x, v.x);
            *(float2*)&As2[kk*ROWP + 2*px2 + 2] = make_float2(v.y, v.y);
        }
        // W tile: [kk][o], LDG.128 along k
        #pragma unroll
        for (int r = 0; r < 8; r++) {
            int i  = tid + 128*r;
            int o  = i >> 3;
            int kt = (i & 7) * 4;
            float4 wv = (o < 123) ? *(const float4*)&w[o*CIN + kc + kt]
                                  : make_float4(0.f, 0.f, 0.f, 0.f);
            Ws[(kt+0)*ROWP + o] = wv.x;
            Ws[(kt+1)*ROWP + o] = wv.y;
            Ws[(kt+2)*ROWP + o] = wv.z;
            Ws[(kt+3)*ROWP + o] = wv.w;
        }
        __syncthreads();
        #pragma unroll
        for (int kk = 0; kk < KC; kk++) {
            ulonglong2 a01 = *(const ulonglong2*)&As2[kk*ROWP + my*16];
            ulonglong2 a23 = *(const ulonglong2*)&As2[kk*ROWP + my*16 + 4];
            ulonglong2 a45 = *(const ulonglong2*)&As2[kk*ROWP + my*16 + 8];
            ulonglong2 a67 = *(const ulonglong2*)&As2[kk*ROWP + my*16 + 12];
            ulonglong2 b03 = *(const ulonglong2*)&Ws[kk*ROWP + ox*8];
            ulonglong2 b47 = *(const ulonglong2*)&Ws[kk*ROWP + ox*8 + 4];
            uint64_t a_[8] = {a01.x, a01.y, a23.x, a23.y, a45.x, a45.y, a67.x, a67.y};
            uint64_t b_[4] = {b03.x, b03.y, b47.x, b47.y};
            #pragma unroll
            for (int i = 0; i < 8; i++) {
                #pragma unroll
                for (int q = 0; q < 4; q++) FFMA2(acc[i][q], a_[i], b_[q]);
            }
        }
        __syncthreads();
    }

    // Epilogue: stage logits tile [64][129] (aliases pool), add bias
    #pragma unroll
    for (int i = 0; i < 8; i++) {
        int m = my*8 + i;
        float v[8];
        #pragma unroll
        for (int q = 0; q < 4; q++) UNPACK2(v[2*q], v[2*q+1], acc[i][q]);
        #pragma unroll
        for (int q = 0; q < 8; q++) {
            int o = ox*8 + q;
            if (o < 123) T[m*129 + o] = v[q] + bias[o];
        }
    }
    __syncthreads();

    // Warp-parallel softmax stats: 4 warps x 16 pixels
    {
        int warp = tid >> 5, lane = tid & 31;
        #pragma unroll
        for (int i = 0; i < 16; i++) {
            int p = warp*16 + i;
            float v0 = (lane      < Dd) ? T[p*129 + lane]      : -3.4e38f;
            float v1 = (lane + 32 < Dd) ? T[p*129 + lane + 32] : -3.4e38f;
            float mx = fmaxf(v0, v1);
            #pragma unroll
            for (int o = 16; o; o >>= 1) mx = fmaxf(mx, __shfl_xor_sync(~0u, mx, o));
            float s = 0.0f;
            if (lane      < Dd) s += expf(v0 - mx);
            if (lane + 32 < Dd) s += expf(v1 - mx);
            #pragma unroll
            for (int o = 16; o; o >>= 1) s += __shfl_xor_sync(~0u, s, o);
            if (lane == 0) { pmax[p] = mx; pinv[p] = 1.0f / s; }
        }
    }
    __syncthreads();

    for (int i = tid; i < TM*Dd; i += 128) {
        int pix = i / Dd;
        int d   = i - pix*Dd;
        depth_out[(size_t)(p0 + pix)*Dd + d] =
            expf(T[pix*129 + d] - pmax[pix]) * pinv[pix];
    }
    for (int i = tid; i < TM*COUT; i += 128) {
        int pix = i >> 6;
        int c   = i & 63;
        g_feat[(size_t)(p0 + pix)*COUT + c] = T[pix*129 + Dd + c];
    }
}

// ---------------------------------------------------------------------------
// Kernel 2: voxel projection + depth-weighted feature splat.
//  Phase A: one projection per lane (one precise rcp), predicated depth LDG,
//           (wgt, feat_off) -> fixed smem slot.
//  Compact: thread-per-x order-preserving in-place squeeze of valid entries.
//  Phase B: half-warp per x, loop only valid entries, 2 per LDS.128,
//           lane owns 4 channels via LDG.128 -> FFMA2.
// ---------------------------------------------------------------------------
#define XQ 32     // x values per block
#define SACCP 68  // sacc row stride (floats)

__global__ __launch_bounds__(256)
void bev_kernel(const float* __restrict__ c2e,
                const float* __restrict__ Kin,
                const float* __restrict__ depth,
                float* __restrict__ bev) {
    __shared__ float2 sl[XQ*42];        // [x][s] (wgt, feat_off_as_float)
    __shared__ float  sacc[XQ*SACCP];   // [x][c]
    __shared__ int    scnt[XQ];
    __shared__ float  sbase[Nc][ZZ][3];
    __shared__ float  scol0[Nc][4];
    __shared__ float  sK[Nc][4];

    const int blk = blockIdx.x;
    const int xq  = blk & 3;
    const int y   = (blk >> 2) & 127;
    const int b   = blk >> 9;
    const int tid = threadIdx.x;
    const float py = y*0.8f - 51.2f;

    if (tid < Nc*ZZ) {
        int n = tid / ZZ, z = tid - n*ZZ;
        const float* m = c2e + (b*Nc + n)*16;   // cam2ego 4x4
        float pz = (float)z - 2.5f;
        // e2c[i][j] = R[j][i];  e2c[i][3] = -sum_j R[j][i]*t[j]
        #pragma unroll
        for (int i = 0; i < 3; i++) {
            float e1 = m[4+i], e2 = m[8+i];
            float e3 = -(m[i]*m[3] + e1*m[7] + e2*m[11]);
            sbase[n][z][i] = py*e1 + pz*e2 + e3;
        }
        if (z == 0) {
            scol0[n][0] = m[0]; scol0[n][1] = m[1]; scol0[n][2] = m[2];
            const float* k = Kin + (b*Nc + n)*9;
            sK[n][0] = k[0]; sK[n][1] = k[4]; sK[n][2] = k[2]; sK[n][3] = k[5];
        }
    }
    __syncthreads();

    // ---- Phase A: per-lane projections (42 samples x 32 x = 1344) ----
    #pragma unroll
    for (int r = 0; r < 6; r++) {
        int idx = tid + 256*r;
        if (idx < Nc*ZZ*XQ) {
            int x = idx & (XQ-1);
            int s = idx >> 5;          // 0..41 (warp-uniform)
            int n = s / ZZ;
            int z = s - n*ZZ;
            float px = (float)(xq*XQ + x)*0.8f - 51.2f;
            float camx = px*scol0[n][0] + sbase[n][z][0];
            float camy = px*scol0[n][1] + sbase[n][z][1];
            float camz = px*scol0[n][2] + sbase[n][z][2];
            float rz   = 1.0f / fmaxf(camz, 0.1f);
            float fu   = (sK[n][0]*(camx*rz) + sK[n][2]) * 0.0625f;
            float fv   = (sK[n][1]*(camy*rz) + sK[n][3]) * 0.0625f;
            int   db   = (int)(camz - 1.0f);   // trunc == numpy astype(int32)
            bool valid = (fu >= 0.0f) && (fu < (float)Wc) &&
                         (fv >= 0.0f) && (fv < (float)Hc) &&
                         (camz > 0.5f) && (db >= 0) && (db < Dd);
            float wgt = 0.0f;
            int   off = 0;
            if (valid) {
                int u = (int)fu;
                int v = (int)fv;
                int p = (b*Nc + n)*HW + v*Wc + u;
                wgt = depth[(size_t)p*Dd + db];
                off = p*COUT;
            }
            sl[x*42 + s] = make_float2(wgt, __int_as_float(off));
        }
    }
    __syncthreads();

    // ---- Compaction: thread x squeezes row x in place (order-preserving) ----
    if (tid < XQ) {
        float2* row = &sl[tid*42];
        int c = 0;
        #pragma unroll 7
        for (int s = 0; s < 42; s++) {
            float2 e = row[s];
            if (e.x != 0.0f) row[c++] = e;
        }
        scnt[tid] = c;
    }
    __syncthreads();

    // ---- Phase B: half-warp per x, 4 channels per lane, valid-only loop ----
    const int warp = tid >> 5;
    const int lane = tid & 31;
    const int xi   = lane >> 4;        // which x of the pair
    const int cl   = lane & 15;        // channel group: c = 4*cl .. 4*cl+3
    const float* fb = g_feat + cl*4;

    #pragma unroll
    for (int it = 0; it < 2; it++) {
        const int x = warp*4 + it*2 + xi;
        const int cnt = scnt[x];
        const float2* row = &sl[x*42];
        uint64_t acc0 = 0, acc1 = 0;   // packed {4cl,4cl+1}, {4cl+2,4cl+3}
        int m2 = cnt & ~1;
        for (int j = 0; j < m2; j += 2) {
            float4 ee = *(const float4*)(row + j);   // two entries
            uint64_t pw0, pw1;
            PACK2S(pw0, ee.x);
            PACK2S(pw1, ee.z);
            ulonglong2 f0 = *(const ulonglong2*)(fb + __float_as_int(ee.y));
            ulonglong2 f1 = *(const ulonglong2*)(fb + __float_as_int(ee.w));
            FFMA2(acc0, pw0, f0.x); FFMA2(acc1, pw0, f0.y);
            FFMA2(acc0, pw1, f1.x); FFMA2(acc1, pw1, f1.y);
        }
        if (cnt & 1) {
            float2 e = row[m2];
            uint64_t pw;
            PACK2S(pw, e.x);
            ulonglong2 f = *(const ulonglong2*)(fb + __float_as_int(e.y));
            FFMA2(acc0, pw, f.x); FFMA2(acc1, pw, f.y);
        }
        float c0, c1, c2, c3;
        UNPACK2(c0, c1, acc0);
        UNPACK2(c2, c3, acc1);
        *(float4*)&sacc[x*SACCP + cl*4] = make_float4(c0, c1, c2, c3);
    }
    __syncthreads();

    // bev[b, c, y, x] — 32-wide contiguous segments
    #pragma unroll
    for (int r = 0; r < 8; r++) {
        int i = tid + 256*r;
        int c = i >> 5;
        int x = i & 31;
        bev[(((size_t)b*COUT + c)*YY + y)*XX + xq*XQ + x] = sacc[x*SACCP + c];
    }
}

// ---------------------------------------------------------------------------
extern "C" void kernel_launch(void* const* d_in, const int* in_sizes, int n_in,
                              void* d_out, int out_size) {
    const float* img  = (const float*)d_in[0];  // (4,6,256,16,44)
    const float* c2e  = (const float*)d_in[1];  // (4,6,4,4)
    const float* Kin  = (const float*)d_in[2];  // (4,6,3,3)
    const float* w    = (const float*)d_in[3];  // (123,256)
    const float* bias = (const float*)d_in[4];  // (123,)
    float* out       = (float*)d_out;
    float* depth_out = out + BEV_SIZE;          // outputs: [bev | depth]

    gemm_softmax<<<NPIX/TM, 128>>>(img, w, bias, depth_out);
    bev_kernel<<<Bc*YY*4, 256>>>(c2e, Kin, depth_out, out);
}

// round 6
// speedup vs baseline: 5.3038x; 1.0487x over previous
#include <cuda_runtime.h>
#include <cstdint>

// Problem constants
#define Bc     4
#define Nc     6
#define CIN    256
#define Hc     16
#define Wc     44
#define Dd     59
#define COUT   64
#define HW     (Hc*Wc)            // 704
#define NPIX   (Bc*Nc*HW)         // 16896
#define XX     128
#define YY     128
#define ZZ     7
#define BEV_SIZE (Bc*COUT*YY*XX)  // 4194304

// Scratch (static device global: no allocation)
__device__ float g_feat[NPIX * COUT];   // (B,N,H*W,64) contiguous, ~4.3MB

// packed fp32x2 helpers (sm_103a FFMA2 — only reachable via PTX)
#define PACK2S(d, v)       asm("mov.b64 %0, {%1, %1};" : "=l"(d) : "f"(v))
#define UNPACK2(lo, hi, s) asm("mov.b64 {%0, %1}, %2;" : "=f"(lo), "=f"(hi) : "l"(s))
#define FFMA2(acc, a, b)   asm("fma.rn.f32x2 %0, %1, %2, %0;" : "+l"(acc) : "l"(a), "l"(b))

// ---------------------------------------------------------------------------
// Kernel 1: per-pixel GEMM (16896 x 123, K=256) + bias + softmax(59) + split
// Tile: 64 pixels x 128 outputs, 128 threads, micro-tile 8 pix x 8 out.
// Thread owns outputs {ox*4..+3} and {64+ox*4..+3} -> both B LDS.128 are
// lane-contiguous 256B blocks (bank-conflict-free). A stored duplicated.
// ---------------------------------------------------------------------------
#define TM 64
#define KC 32
#define ROWP 132   // padded row (floats)

__global__ __launch_bounds__(128)
void gemm_softmax(const float* __restrict__ img,
                  const float* __restrict__ w,
                  const float* __restrict__ bias,
                  float* __restrict__ depth_out) {
    __shared__ float pool[2*KC*ROWP];   // As2 | Ws; reused as T[64*129] after loop
    __shared__ float pmax[TM], pinv[TM];
    float* As2 = pool;                  // [kk][2*pix] (duplicated pairs)
    float* Ws  = pool + KC*ROWP;        // [kk][o]
    float* T   = pool;                  // logits tile [pix][129] (aliases)

    const int p0  = blockIdx.x * TM;      // 704 % 64 == 0 -> tile within one (b,n)
    const int bn  = p0 / HW;
    const int hw0 = p0 - bn*HW;
    const float* abase = img + (size_t)bn*CIN*HW + hw0;

    const int tid = threadIdx.x;
    const int ox  = tid & 15;             // outputs ox*4..+3 and 64+ox*4..+3
    const int my  = tid >> 4;             // pixels  my*8 .. my*8+7

    uint64_t acc[8][4] = {};              // [pix][{lo0,lo1,hi0,hi1}]

    for (int kc = 0; kc < CIN; kc += KC) {
        // A tile: 64 pix x 32 kk, LDG.64 + duplicated STS
        #pragma unroll
        for (int r = 0; r < 8; r++) {
            int i   = tid + 128*r;
            int kk  = i >> 5;
            int px2 = (i & 31) * 2;
            float2 v = *(const float2*)&abase[(size_t)(kc+kk)*HW + px2];
            *(float2*)&As2[kk*ROWP + 2*px2]     = make_float2(v.x, v.x);
            *(float2*)&As2[kk*ROWP + 2*px2 + 2] = make_float2(v.y, v.y);
        }
        // W tile: [kk][o], LDG.128 along k
        #pragma unroll
        for (int r = 0; r < 8; r++) {
            int i  = tid + 128*r;
            int o  = i >> 3;
            int kt = (i & 7) * 4;
            float4 wv = (o < 123) ? *(const float4*)&w[o*CIN + kc + kt]
                                  : make_float4(0.f, 0.f, 0.f, 0.f);
            Ws[(kt+0)*ROWP + o] = wv.x;
            Ws[(kt+1)*ROWP + o] = wv.y;
            Ws[(kt+2)*ROWP + o] = wv.z;
            Ws[(kt+3)*ROWP + o] = wv.w;
        }
        __syncthreads();
        #pragma unroll
        for (int kk = 0; kk < KC; kk++) {
            ulonglong2 a01 = *(const ulonglong2*)&As2[kk*ROWP + my*16];
            ulonglong2 a23 = *(const ulonglong2*)&As2[kk*ROWP + my*16 + 4];
            ulonglong2 a45 = *(const ulonglong2*)&As2[kk*ROWP + my*16 + 8];
            ulonglong2 a67 = *(const ulonglong2*)&As2[kk*ROWP + my*16 + 12];
            ulonglong2 blo = *(const ulonglong2*)&Ws[kk*ROWP + ox*4];       // o=ox*4..+3
            ulonglong2 bhi = *(const ulonglong2*)&Ws[kk*ROWP + 64 + ox*4];  // o=64+ox*4..+3
            uint64_t a_[8] = {a01.x, a01.y, a23.x, a23.y, a45.x, a45.y, a67.x, a67.y};
            uint64_t b_[4] = {blo.x, blo.y, bhi.x, bhi.y};
            #pragma unroll
            for (int i = 0; i < 8; i++) {
                #pragma unroll
                for (int q = 0; q < 4; q++) FFMA2(acc[i][q], a_[i], b_[q]);
            }
        }
        __syncthreads();
    }

    // Epilogue: stage logits tile [64][129] (aliases pool), add bias
    #pragma unroll
    for (int i = 0; i < 8; i++) {
        int m = my*8 + i;
        float v[8];
        #pragma unroll
        for (int q = 0; q < 4; q++) UNPACK2(v[2*q], v[2*q+1], acc[i][q]);
        #pragma unroll
        for (int q = 0; q < 4; q++) {
            int o = ox*4 + q;                 // < 64, always valid
            T[m*129 + o] = v[q] + bias[o];
        }
        #pragma unroll
        for (int q = 0; q < 4; q++) {
            int o = 64 + ox*4 + q;
            if (o < 123) T[m*129 + o] = v[4+q] + bias[o];
        }
    }
    __syncthreads();

    // Warp-parallel softmax stats: 4 warps x 16 pixels
    {
        int warp = tid >> 5, lane = tid & 31;
        #pragma unroll
        for (int i = 0; i < 16; i++) {
            int p = warp*16 + i;
            float v0 = (lane      < Dd) ? T[p*129 + lane]      : -3.4e38f;
            float v1 = (lane + 32 < Dd) ? T[p*129 + lane + 32] : -3.4e38f;
            float mx = fmaxf(v0, v1);
            #pragma unroll
            for (int o = 16; o; o >>= 1) mx = fmaxf(mx, __shfl_xor_sync(~0u, mx, o));
            float s = 0.0f;
            if (lane      < Dd) s += expf(v0 - mx);
            if (lane + 32 < Dd) s += expf(v1 - mx);
            #pragma unroll
            for (int o = 16; o; o >>= 1) s += __shfl_xor_sync(~0u, s, o);
            if (lane == 0) { pmax[p] = mx; pinv[p] = 1.0f / s; }
        }
    }
    __syncthreads();

    for (int i = tid; i < TM*Dd; i += 128) {
        int pix = i / Dd;
        int d   = i - pix*Dd;
        depth_out[(size_t)(p0 + pix)*Dd + d] =
            expf(T[pix*129 + d] - pmax[pix]) * pinv[pix];
    }
    for (int i = tid; i < TM*COUT; i += 128) {
        int pix = i >> 6;
        int c   = i & 63;
        g_feat[(size_t)(p0 + pix)*COUT + c] = T[pix*129 + Dd + c];
    }
}

// ---------------------------------------------------------------------------
// Kernel 2: voxel projection + depth-weighted feature splat.
//  Phase A: one projection per lane, predicated depth LDG.
//  Compact: thread-per-x in-place squeeze of valid entries (order-preserving).
//  Phase B: half-warp per x, valid-only loop unrolled x4 (MLP=4 LDG.128).
// ---------------------------------------------------------------------------
#define XQ 32     // x values per block
#define SACCP 68  // sacc row stride (floats)

__global__ __launch_bounds__(256, 6)
void bev_kernel(const float* __restrict__ c2e,
                const float* __restrict__ Kin,
                const float* __restrict__ depth,
                float* __restrict__ bev) {
    __shared__ float2 sl[XQ*42];        // [x][s] (wgt, feat_off_as_float)
    __shared__ float  sacc[XQ*SACCP];   // [x][c]
    __shared__ int    scnt[XQ];
    __shared__ float  sbase[Nc][ZZ][3];
    __shared__ float  scol0[Nc][4];
    __shared__ float  sK[Nc][4];

    const int blk = blockIdx.x;
    const int xq  = blk & 3;
    const int y   = (blk >> 2) & 127;
    const int b   = blk >> 9;
    const int tid = threadIdx.x;
    const float py = y*0.8f - 51.2f;

    if (tid < Nc*ZZ) {
        int n = tid / ZZ, z = tid - n*ZZ;
        const float* m = c2e + (b*Nc + n)*16;   // cam2ego 4x4
        float pz = (float)z - 2.5f;
        // e2c[i][j] = R[j][i];  e2c[i][3] = -sum_j R[j][i]*t[j]
        #pragma unroll
        for (int i = 0; i < 3; i++) {
            float e1 = m[4+i], e2 = m[8+i];
            float e3 = -(m[i]*m[3] + e1*m[7] + e2*m[11]);
            sbase[n][z][i] = py*e1 + pz*e2 + e3;
        }
        if (z == 0) {
            scol0[n][0] = m[0]; scol0[n][1] = m[1]; scol0[n][2] = m[2];
            const float* k = Kin + (b*Nc + n)*9;
            sK[n][0] = k[0]; sK[n][1] = k[4]; sK[n][2] = k[2]; sK[n][3] = k[5];
        }
    }
    __syncthreads();

    // ---- Phase A: per-lane projections (42 samples x 32 x = 1344) ----
    #pragma unroll
    for (int r = 0; r < 6; r++) {
        int idx = tid + 256*r;
        if (idx < Nc*ZZ*XQ) {
            int x = idx & (XQ-1);
            int s = idx >> 5;          // 0..41 (warp-uniform)
            int n = s / ZZ;
            int z = s - n*ZZ;
            float px = (float)(xq*XQ + x)*0.8f - 51.2f;
            float camx = px*scol0[n][0] + sbase[n][z][0];
            float camy = px*scol0[n][1] + sbase[n][z][1];
            float camz = px*scol0[n][2] + sbase[n][z][2];
            float rz   = 1.0f / fmaxf(camz, 0.1f);
            float fu   = (sK[n][0]*(camx*rz) + sK[n][2]) * 0.0625f;
            float fv   = (sK[n][1]*(camy*rz) + sK[n][3]) * 0.0625f;
            int   db   = (int)(camz - 1.0f);   // trunc == numpy astype(int32)
            bool valid = (fu >= 0.0f) && (fu < (float)Wc) &&
                         (fv >= 0.0f) && (fv < (float)Hc) &&
                         (camz > 0.5f) && (db >= 0) && (db < Dd);
            float wgt = 0.0f;
            int   off = 0;
            if (valid) {
                int u = (int)fu;
                int v = (int)fv;
                int p = (b*Nc + n)*HW + v*Wc + u;
                wgt = depth[(size_t)p*Dd + db];
                off = p*COUT;
            }
            sl[x*42 + s] = make_float2(wgt, __int_as_float(off));
        }
    }
    __syncthreads();

    // ---- Compaction: thread x squeezes row x in place (order-preserving) ----
    if (tid < XQ) {
        float2* row = &sl[tid*42];
        int c = 0;
        #pragma unroll 7
        for (int s = 0; s < 42; s++) {
            float2 e = row[s];
            if (e.x != 0.0f) row[c++] = e;
        }
        scnt[tid] = c;
    }
    __syncthreads();

    // ---- Phase B: half-warp per x, 4 channels per lane, valid-only loop ----
    const int warp = tid >> 5;
    const int lane = tid & 31;
    const int xi   = lane >> 4;        // which x of the pair
    const int cl   = lane & 15;        // channel group: c = 4*cl .. 4*cl+3
    const float* fb = g_feat + cl*4;

    #pragma unroll
    for (int it = 0; it < 2; it++) {
        const int x = warp*4 + it*2 + xi;
        const int cnt = scnt[x];
        const float2* row = &sl[x*42];
        uint64_t acc0 = 0, acc1 = 0;   // packed {4cl,4cl+1}, {4cl+2,4cl+3}
        int j = 0;
        // 4-entry unrolled body: 4 independent LDG.128 in flight
        for (; j + 4 <= cnt; j += 4) {
            float4 e0 = *(const float4*)(row + j);       // entries j, j+1
            float4 e1 = *(const float4*)(row + j + 2);   // entries j+2, j+3
            ulonglong2 f0 = *(const ulonglong2*)(fb + __float_as_int(e0.y));
            ulonglong2 f1 = *(const ulonglong2*)(fb + __float_as_int(e0.w));
            ulonglong2 f2 = *(const ulonglong2*)(fb + __float_as_int(e1.y));
            ulonglong2 f3 = *(const ulonglong2*)(fb + __float_as_int(e1.w));
            uint64_t p0, p1, p2, p3;
            PACK2S(p0, e0.x); PACK2S(p1, e0.z);
            PACK2S(p2, e1.x); PACK2S(p3, e1.z);
            FFMA2(acc0, p0, f0.x); FFMA2(acc1, p0, f0.y);
            FFMA2(acc0, p1, f1.x); FFMA2(acc1, p1, f1.y);
            FFMA2(acc0, p2, f2.x); FFMA2(acc1, p2, f2.y);
            FFMA2(acc0, p3, f3.x); FFMA2(acc1, p3, f3.y);
        }
        for (; j < cnt; j++) {
            float2 e = row[j];
            uint64_t pw;
            PACK2S(pw, e.x);
            ulonglong2 f = *(const ulonglong2*)(fb + __float_as_int(e.y));
            FFMA2(acc0, pw, f.x); FFMA2(acc1, pw, f.y);
        }
        float c0, c1, c2, c3;
        UNPACK2(c0, c1, acc0);
        UNPACK2(c2, c3, acc1);
        *(float4*)&sacc[x*SACCP + cl*4] = make_float4(c0, c1, c2, c3);
    }
    __syncthreads();

    // bev[b, c, y, x] — 32-wide contiguous segments
    #pragma unroll
    for (int r = 0; r < 8; r++) {
        int i = tid + 256*r;
        int c = i >> 5;
        int x = i & 31;
        bev[(((size_t)b*COUT + c)*YY + y)*XX + xq*XQ + x] = sacc[x*SACCP + c];
    }
}

// ---------------------------------------------------------------------------
extern "C" void kernel_launch(void* const* d_in, const int* in_sizes, int n_in,
                              void* d_out, int out_size) {
    const float* img  = (const float*)d_in[0];  // (4,6,256,16,44)
    const float* c2e  = (const float*)d_in[1];  // (4,6,4,4)
    const float* Kin  = (const float*)d_in[2];  // (4,6,3,3)
    const float* w    = (const float*)d_in[3];  // (123,256)
    const float* bias = (const float*)d_in[4];  // (123,)
    float* out       = (float*)d_out;
    float* depth_out = out + BEV_SIZE;          // outputs: [bev | depth]

    gemm_softmax<<<NPIX/TM, 128>>>(img, w, bias, depth_out);
    bev_kernel<<<Bc*YY*4, 256>>>(c2e, Kin, depth_out, out);
}

// round 8
// speedup vs baseline: 6.2384x; 1.1762x over previous
#include <cuda_runtime.h>
#include <cuda_bf16.h>
#include <cstdint>

// Problem constants
#define Bc     4
#define Nc     6
#define CIN    256
#define Hc     16
#define Wc     44
#define Dd     59
#define COUT   64
#define HW     (Hc*Wc)            // 704
#define NPIX   (Bc*Nc*HW)         // 16896
#define XX     128
#define YY     128
#define ZZ     7
#define BEV_SIZE (Bc*COUT*YY*XX)  // 4194304

// Scratch (static device global: no allocation)
__device__ float g_feat[NPIX * COUT];   // (B,N,H*W,64) contiguous, ~4.3MB

// packed fp32x2 helpers (bev kernel)
#define PACK2S(d, v)       asm("mov.b64 %0, {%1, %1};" : "=l"(d) : "f"(v))
#define UNPACK2(lo, hi, s) asm("mov.b64 {%0, %1}, %2;" : "=f"(lo), "=f"(hi) : "l"(s))
#define FFMA2(acc, a, b)   asm("fma.rn.f32x2 %0, %1, %2, %0;" : "+l"(acc) : "l"(a), "l"(b))

// bf16 hi/lo split of two floats, packed along k: lower half = x0, upper = x1
__device__ __forceinline__ void bfsplit2(float x0, float x1, uint32_t& hi, uint32_t& lo) {
    asm("cvt.rn.bf16x2.f32 %0, %1, %2;" : "=r"(hi) : "f"(x1), "f"(x0));
    float h0 = __uint_as_float(hi << 16);
    float h1 = __uint_as_float(hi & 0xffff0000u);
    float r0 = x0 - h0, r1 = x1 - h1;
    asm("cvt.rn.bf16x2.f32 %0, %1, %2;" : "=r"(lo) : "f"(r1), "f"(r0));
}

#define MMA_BF16(d, a, b0, b1) \
    asm volatile("mma.sync.aligned.m16n8k16.row.col.f32.bf16.bf16.f32 " \
        "{%0,%1,%2,%3}, {%4,%5,%6,%7}, {%8,%9}, {%0,%1,%2,%3};" \
        : "+f"((d)[0]), "+f"((d)[1]), "+f"((d)[2]), "+f"((d)[3]) \
        : "r"((a)[0]), "r"((a)[1]), "r"((a)[2]), "r"((a)[3]), "r"(b0), "r"(b1))

// ---------------------------------------------------------------------------
// Kernel 1: bf16 3-pass mma.sync GEMM (128 pix x 128 out, K=256) + bias +
// softmax(59) + split. 128 threads = 4 warps, each warp owns a 64x64 tile.
// SMEM: k-pair-major tiles [j][pix]/[j][o], stride 136 words (conflict-free
// fragment loads: banks = 8*tig + g, a 0..31 permutation).
// D = Ah*Bh + Ah*Bl + Al*Bh  (error ~2^-16, gate is 1e-3).
// ---------------------------------------------------------------------------
#define TILE_M 128
#define KCH    64
#define SSTR   136                 // words per j-row
#define TWORDS (32*SSTR)           // 4352 words per tile

__global__ __launch_bounds__(128)
void gemm_mma(const float* __restrict__ img,
              const float* __restrict__ w,
              const float* __restrict__ bias,
              float* __restrict__ depth_out) {
    extern __shared__ uint32_t sm[];           // aHi|aLo|bHi|bLo; later T
    __shared__ float sbias[128];
    __shared__ int   sgb[32];
    __shared__ float pmax[TILE_M], pinv[TILE_M];

    uint32_t* aHi = sm;
    uint32_t* aLo = sm + TWORDS;
    uint32_t* bHi = sm + 2*TWORDS;
    uint32_t* bLo = sm + 3*TWORDS;
    float*    T   = (float*)sm;                // logits tile [128][129] (alias)

    const int tid  = threadIdx.x;
    const int wid  = tid >> 5;
    const int lane = tid & 31;
    const int g    = lane >> 2;                // group id (0..7)
    const int tig  = lane & 3;                 // thread in group
    const int wr   = wid & 1;                  // pixel half (64)
    const int wc   = wid >> 1;                 // output half (64)
    const int p0   = blockIdx.x * TILE_M;

    if (tid < 32) {
        int p = p0 + tid*4;                    // HW%4==0 -> group stays in one bn
        int bn = p / HW;
        sgb[tid] = bn*CIN*HW + (p - bn*HW);
    }
    sbias[tid] = (tid < 123) ? bias[tid] : 0.0f;
    __syncthreads();

    float acc[4][8][4] = {};                   // [mt][nt][c-frag]

    for (int ch = 0; ch < 4; ch++) {
        const int kc = ch * KCH;
        // ---- stage A: 128 pix x 64 k -> 32 j-rows of bf16x2 pairs ----
        #pragma unroll
        for (int r = 0; r < 8; r++) {
            int idx = tid + 128*r;
            int gg = idx & 31;                 // pixel group
            int j  = idx >> 5;                 // k-pair row (0..31)
            const float* base = img + sgb[gg] + (size_t)(kc + 2*j)*HW;
            float4 v0 = *(const float4*)base;        // 4 pixels @ k
            float4 v1 = *(const float4*)(base + HW); // 4 pixels @ k+1
            uint32_t h[4], l[4];
            bfsplit2(v0.x, v1.x, h[0], l[0]);
            bfsplit2(v0.y, v1.y, h[1], l[1]);
            bfsplit2(v0.z, v1.z, h[2], l[2]);
            bfsplit2(v0.w, v1.w, h[3], l[3]);
            *(uint4*)&aHi[j*SSTR + 4*gg] = make_uint4(h[0], h[1], h[2], h[3]);
            *(uint4*)&aLo[j*SSTR + 4*gg] = make_uint4(l[0], l[1], l[2], l[3]);
        }
        // ---- stage B: 128 out x 64 k; thread owns output o = tid ----
        {
            const float* wb = w + (size_t)tid*CIN + kc;
            #pragma unroll
            for (int kg = 0; kg < 16; kg++) {
                float4 v = (tid < 123) ? *(const float4*)(wb + 4*kg)
                                       : make_float4(0.f, 0.f, 0.f, 0.f);
                uint32_t h0, l0, h1, l1;
                bfsplit2(v.x, v.y, h0, l0);
                bfsplit2(v.z, v.w, h1, l1);
                bHi[(2*kg  )*SSTR + tid] = h0;
                bHi[(2*kg+1)*SSTR + tid] = h1;
                bLo[(2*kg  )*SSTR + tid] = l0;
                bLo[(2*kg+1)*SSTR + tid] = l1;
            }
        }
        __syncthreads();

        // ---- mma: 3 passes x 4 ksteps (k16) ----
        #pragma unroll
        for (int pass = 0; pass < 3; pass++) {
            const uint32_t* aB = (pass == 2) ? aLo : aHi;
            const uint32_t* bB = (pass == 1) ? bLo : bHi;
            #pragma unroll
            for (int ks = 0; ks < 4; ks++) {
                const int j0 = ks*8;
                uint32_t afr[4][4];
                #pragma unroll
                for (int mt = 0; mt < 4; mt++) {
                    int m0 = wr*64 + mt*16;
                    afr[mt][0] = aB[(j0+tig  )*SSTR + m0 + g    ];
                    afr[mt][1] = aB[(j0+tig  )*SSTR + m0 + g + 8];
                    afr[mt][2] = aB[(j0+tig+4)*SSTR + m0 + g    ];
                    afr[mt][3] = aB[(j0+tig+4)*SSTR + m0 + g + 8];
                }
                #pragma unroll
                for (int nt = 0; nt < 8; nt++) {
                    int n0 = wc*64 + nt*8;
                    uint32_t b0 = bB[(j0+tig  )*SSTR + n0 + g];
                    uint32_t b1 = bB[(j0+tig+4)*SSTR + n0 + g];
                    #pragma unroll
                    for (int mt = 0; mt < 4; mt++)
                        MMA_BF16(acc[mt][nt], afr[mt], b0, b1);
                }
            }
        }
        __syncthreads();   // mma done before next chunk restages (or T write)
    }

    // ---- Epilogue: acc -> T[pix][129] with bias ----
    #pragma unroll
    for (int mt = 0; mt < 4; mt++) {
        #pragma unroll
        for (int nt = 0; nt < 8; nt++) {
            int row0 = wr*64 + mt*16 + g;
            int col  = wc*64 + nt*8 + 2*tig;
            T[ row0   *129 + col    ] = acc[mt][nt][0] + sbias[col];
            T[ row0   *129 + col + 1] = acc[mt][nt][1] + sbias[col+1];
            T[(row0+8)*129 + col    ] = acc[mt][nt][2] + sbias[col];
            T[(row0+8)*129 + col + 1] = acc[mt][nt][3] + sbias[col+1];
        }
    }
    __syncthreads();

    // Warp-parallel softmax stats: 4 warps x 32 pixels
    #pragma unroll
    for (int i = 0; i < 32; i++) {
        int p = wid*32 + i;
        float v0 = (lane      < Dd) ? T[p*129 + lane]      : -3.4e38f;
        float v1 = (lane + 32 < Dd) ? T[p*129 + lane + 32] : -3.4e38f;
        float mx = fmaxf(v0, v1);
        #pragma unroll
        for (int o = 16; o; o >>= 1) mx = fmaxf(mx, __shfl_xor_sync(~0u, mx, o));
        float s = 0.0f;
        if (lane      < Dd) s += expf(v0 - mx);
        if (lane + 32 < Dd) s += expf(v1 - mx);
        #pragma unroll
        for (int o = 16; o; o >>= 1) s += __shfl_xor_sync(~0u, s, o);
        if (lane == 0) { pmax[p] = mx; pinv[p] = 1.0f / s; }
    }
    __syncthreads();

    for (int i = tid; i < TILE_M*Dd; i += 128) {
        int pix = i / Dd;
        int d   = i - pix*Dd;
        depth_out[(size_t)(p0 + pix)*Dd + d] =
            expf(T[pix*129 + d] - pmax[pix]) * pinv[pix];
    }
    for (int i = tid; i < TILE_M*COUT; i += 128) {
        int pix = i >> 6;
        int c   = i & 63;
        g_feat[(size_t)(p0 + pix)*COUT + c] = T[pix*129 + Dd + c];
    }
}

// ---------------------------------------------------------------------------
// Kernel 2: voxel projection + depth-weighted feature splat (R5 form).
// ---------------------------------------------------------------------------
#define XQ 32     // x values per block
#define SACCP 68  // sacc row stride (floats)

__global__ __launch_bounds__(256)
void bev_kernel(const float* __restrict__ c2e,
                const float* __restrict__ Kin,
                const float* __restrict__ depth,
                float* __restrict__ bev) {
    __shared__ float2 sl[XQ*42];        // [x][s] (wgt, feat_off_as_float)
    __shared__ float  sacc[XQ*SACCP];   // [x][c]
    __shared__ int    scnt[XQ];
    __shared__ float  sbase[Nc][ZZ][3];
    __shared__ float  scol0[Nc][4];
    __shared__ float  sK[Nc][4];

    const int blk = blockIdx.x;
    const int xq  = blk & 3;
    const int y   = (blk >> 2) & 127;
    const int b   = blk >> 9;
    const int tid = threadIdx.x;
    const float py = y*0.8f - 51.2f;

    if (tid < Nc*ZZ) {
        int n = tid / ZZ, z = tid - n*ZZ;
        const float* m = c2e + (b*Nc + n)*16;   // cam2ego 4x4
        float pz = (float)z - 2.5f;
        #pragma unroll
        for (int i = 0; i < 3; i++) {
            float e1 = m[4+i], e2 = m[8+i];
            float e3 = -(m[i]*m[3] + e1*m[7] + e2*m[11]);
            sbase[n][z][i] = py*e1 + pz*e2 + e3;
        }
        if (z == 0) {
            scol0[n][0] = m[0]; scol0[n][1] = m[1]; scol0[n][2] = m[2];
            const float* k = Kin + (b*Nc + n)*9;
            sK[n][0] = k[0]; sK[n][1] = k[4]; sK[n][2] = k[2]; sK[n][3] = k[5];
        }
    }
    __syncthreads();

    // ---- Phase A: per-lane projections (42 samples x 32 x = 1344) ----
    #pragma unroll
    for (int r = 0; r < 6; r++) {
        int idx = tid + 256*r;
        if (idx < Nc*ZZ*XQ) {
            int x = idx & (XQ-1);
            int s = idx >> 5;          // 0..41 (warp-uniform)
            int n = s / ZZ;
            int z = s - n*ZZ;
            float px = (float)(xq*XQ + x)*0.8f - 51.2f;
            float camx = px*scol0[n][0] + sbase[n][z][0];
            float camy = px*scol0[n][1] + sbase[n][z][1];
            float camz = px*scol0[n][2] + sbase[n][z][2];
            float rz   = 1.0f / fmaxf(camz, 0.1f);
            float fu   = (sK[n][0]*(camx*rz) + sK[n][2]) * 0.0625f;
            float fv   = (sK[n][1]*(camy*rz) + sK[n][3]) * 0.0625f;
            int   db   = (int)(camz - 1.0f);   // trunc == numpy astype(int32)
            bool valid = (fu >= 0.0f) && (fu < (float)Wc) &&
                         (fv >= 0.0f) && (fv < (float)Hc) &&
                         (camz > 0.5f) && (db >= 0) && (db < Dd);
            float wgt = 0.0f;
            int   off = 0;
            if (valid) {
                int u = (int)fu;
                int v = (int)fv;
                int pp = (b*Nc + n)*HW + v*Wc + u;
                wgt = depth[(size_t)pp*Dd + db];
                off = pp*COUT;
            }
            sl[x*42 + s] = make_float2(wgt, __int_as_float(off));
        }
    }
    __syncthreads();

    // ---- Compaction: thread x squeezes row x in place (order-preserving) ----
    if (tid < XQ) {
        float2* row = &sl[tid*42];
        int c = 0;
        #pragma unroll 7
        for (int s = 0; s < 42; s++) {
            float2 e = row[s];
            if (e.x != 0.0f) row[c++] = e;
        }
        scnt[tid] = c;
    }
    __syncthreads();

    // ---- Phase B: half-warp per x, 4 channels per lane, valid-only loop ----
    const int warp = tid >> 5;
    const int lane = tid & 31;
    const int xi   = lane >> 4;        // which x of the pair
    const int cl   = lane & 15;        // channel group: c = 4*cl .. 4*cl+3
    const float* fb = g_feat + cl*4;

    #pragma unroll
    for (int it = 0; it < 2; it++) {
        const int x = warp*4 + it*2 + xi;
        const int cnt = scnt[x];
        const float2* row = &sl[x*42];
        uint64_t acc0 = 0, acc1 = 0;   // packed {4cl,4cl+1}, {4cl+2,4cl+3}
        int m2 = cnt & ~1;
        for (int j = 0; j < m2; j += 2) {
            float4 ee = *(const float4*)(row + j);   // two entries
            uint64_t pw0, pw1;
            PACK2S(pw0, ee.x);
            PACK2S(pw1, ee.z);
            ulonglong2 f0 = *(const ulonglong2*)(fb + __float_as_int(ee.y));
            ulonglong2 f1 = *(const ulonglong2*)(fb + __float_as_int(ee.w));
            FFMA2(acc0, pw0, f0.x); FFMA2(acc1, pw0, f0.y);
            FFMA2(acc0, pw1, f1.x); FFMA2(acc1, pw1, f1.y);
        }
        if (cnt & 1) {
            float2 e = row[m2];
            uint64_t pw;
            PACK2S(pw, e.x);
            ulonglong2 f = *(const ulonglong2*)(fb + __float_as_int(e.y));
            FFMA2(acc0, pw, f.x); FFMA2(acc1, pw, f.y);
        }
        float c0, c1, c2, c3;
        UNPACK2(c0, c1, acc0);
        UNPACK2(c2, c3, acc1);
        *(float4*)&sacc[x*SACCP + cl*4] = make_float4(c0, c1, c2, c3);
    }
    __syncthreads();

    // bev[b, c, y, x] — 32-wide contiguous segments
    #pragma unroll
    for (int r = 0; r < 8; r++) {
        int i = tid + 256*r;
        int c = i >> 5;
        int x = i & 31;
        bev[(((size_t)b*COUT + c)*YY + y)*XX + xq*XQ + x] = sacc[x*SACCP + c];
    }
}

// ---------------------------------------------------------------------------
extern "C" void kernel_launch(void* const* d_in, const int* in_sizes, int n_in,
                              void* d_out, int out_size) {
    const float* img  = (const float*)d_in[0];  // (4,6,256,16,44)
    const float* c2e  = (const float*)d_in[1];  // (4,6,4,4)
    const float* Kin  = (const float*)d_in[2];  // (4,6,3,3)
    const float* w    = (const float*)d_in[3];  // (123,256)
    const float* bias = (const float*)d_in[4];  // (123,)
    float* out       = (float*)d_out;
    float* depth_out = out + BEV_SIZE;          // outputs: [bev | depth]

    const int smem_bytes = 4*TWORDS*4;          // 69632 B
    cudaFuncSetAttribute(gemm_mma, cudaFuncAttributeMaxDynamicSharedMemorySize, smem_bytes);

    gemm_mma<<<NPIX/TILE_M, 128, smem_bytes>>>(img, w, bias, depth_out);
    bev_kernel<<<Bc*YY*4, 256>>>(c2e, Kin, depth_out, out);
}

// round 9
// speedup vs baseline: 6.6020x; 1.0583x over previous
#include <cuda_runtime.h>
#include <cuda_bf16.h>
#include <cstdint>

// Problem constants
#define Bc     4
#define Nc     6
#define CIN    256
#define Hc     16
#define Wc     44
#define Dd     59
#define COUT   64
#define HW     (Hc*Wc)            // 704
#define NPIX   (Bc*Nc*HW)         // 16896
#define XX     128
#define YY     128
#define ZZ     7
#define BEV_SIZE (Bc*COUT*YY*XX)  // 4194304

// Scratch (static device global: no allocation)
__device__ float g_feat[NPIX * COUT];   // (B,N,H*W,64) contiguous, ~4.3MB

// packed fp32x2 helpers (bev kernel)
#define PACK2S(d, v)       asm("mov.b64 %0, {%1, %1};" : "=l"(d) : "f"(v))
#define UNPACK2(lo, hi, s) asm("mov.b64 {%0, %1}, %2;" : "=f"(lo), "=f"(hi) : "l"(s))
#define FFMA2(acc, a, b)   asm("fma.rn.f32x2 %0, %1, %2, %0;" : "+l"(acc) : "l"(a), "l"(b))

// bf16 hi/lo split of two floats, packed along k: lower half = x0, upper = x1
__device__ __forceinline__ void bfsplit2(float x0, float x1, uint32_t& hi, uint32_t& lo) {
    asm("cvt.rn.bf16x2.f32 %0, %1, %2;" : "=r"(hi) : "f"(x1), "f"(x0));
    float h0 = __uint_as_float(hi << 16);
    float h1 = __uint_as_float(hi & 0xffff0000u);
    float r0 = x0 - h0, r1 = x1 - h1;
    asm("cvt.rn.bf16x2.f32 %0, %1, %2;" : "=r"(lo) : "f"(r1), "f"(r0));
}

#define MMA_BF16(d, a, b0, b1) \
    asm volatile("mma.sync.aligned.m16n8k16.row.col.f32.bf16.bf16.f32 " \
        "{%0,%1,%2,%3}, {%4,%5,%6,%7}, {%8,%9}, {%0,%1,%2,%3};" \
        : "+f"((d)[0]), "+f"((d)[1]), "+f"((d)[2]), "+f"((d)[3]) \
        : "r"((a)[0]), "r"((a)[1]), "r"((a)[2]), "r"((a)[3]), "r"(b0), "r"(b1))

// ---------------------------------------------------------------------------
// Kernel 1: bf16 3-pass mma.sync GEMM (128 pix x 128 out, K=256) + bias +
// softmax(59) + split. 256 threads = 8 warps, warp tile 64 pix x 32 out
// (2 warps/SMSP -> LDS->MMA latency hidden).
// SMEM: k-pair-major tiles [j][pix]/[j][o], stride 136 words (conflict-free).
// D = Ah*Bh + Ah*Bl + Al*Bh  (error ~2^-16, gate is 1e-3).
// ---------------------------------------------------------------------------
#define TILE_M 128
#define KCH    64
#define SSTR   136                 // words per j-row
#define TWORDS (32*SSTR)           // 4352 words per tile

__global__ __launch_bounds__(256)
void gemm_mma(const float* __restrict__ img,
              const float* __restrict__ w,
              const float* __restrict__ bias,
              float* __restrict__ depth_out) {
    extern __shared__ uint32_t sm[];           // aHi|aLo|bHi|bLo; later T
    __shared__ float sbias[128];
    __shared__ int   sgb[32];
    __shared__ float pmax[TILE_M], pinv[TILE_M];

    uint32_t* aHi = sm;
    uint32_t* aLo = sm + TWORDS;
    uint32_t* bHi = sm + 2*TWORDS;
    uint32_t* bLo = sm + 3*TWORDS;
    float*    T   = (float*)sm;                // logits tile [128][129] (alias)

    const int tid  = threadIdx.x;
    const int wid  = tid >> 5;
    const int lane = tid & 31;
    const int g    = lane >> 2;                // group id (0..7)
    const int tig  = lane & 3;                 // thread in group
    const int wr   = wid & 1;                  // pixel half (64)
    const int wc   = wid >> 1;                 // output quarter (32)
    const int p0   = blockIdx.x * TILE_M;

    if (tid < 32) {
        int p = p0 + tid*4;                    // HW%4==0 -> group stays in one bn
        int bn = p / HW;
        sgb[tid] = bn*CIN*HW + (p - bn*HW);
    }
    if (tid < 128) sbias[tid] = (tid < 123) ? bias[tid] : 0.0f;
    __syncthreads();

    float acc[4][4][4] = {};                   // [mt][nt][c-frag]

    for (int ch = 0; ch < 4; ch++) {
        const int kc = ch * KCH;
        // ---- stage A: 128 pix x 64 k -> 32 j-rows of bf16x2 pairs ----
        #pragma unroll
        for (int r = 0; r < 4; r++) {
            int idx = tid + 256*r;
            int gg = idx & 31;                 // pixel group
            int j  = idx >> 5;                 // k-pair row (0..31)
            const float* base = img + sgb[gg] + (size_t)(kc + 2*j)*HW;
            float4 v0 = *(const float4*)base;        // 4 pixels @ k
            float4 v1 = *(const float4*)(base + HW); // 4 pixels @ k+1
            uint32_t h[4], l[4];
            bfsplit2(v0.x, v1.x, h[0], l[0]);
            bfsplit2(v0.y, v1.y, h[1], l[1]);
            bfsplit2(v0.z, v1.z, h[2], l[2]);
            bfsplit2(v0.w, v1.w, h[3], l[3]);
            *(uint4*)&aHi[j*SSTR + 4*gg] = make_uint4(h[0], h[1], h[2], h[3]);
            *(uint4*)&aLo[j*SSTR + 4*gg] = make_uint4(l[0], l[1], l[2], l[3]);
        }
        // ---- stage B: 128 out x 64 k; two threads split one output row ----
        {
            const int o    = tid & 127;
            const int half = tid >> 7;          // kg 0..7 or 8..15
            const float* wb = w + (size_t)o*CIN + kc;
            #pragma unroll
            for (int kq = 0; kq < 8; kq++) {
                int kg = half*8 + kq;
                float4 v = (o < 123) ? *(const float4*)(wb + 4*kg)
                                     : make_float4(0.f, 0.f, 0.f, 0.f);
                uint32_t h0, l0, h1, l1;
                bfsplit2(v.x, v.y, h0, l0);
                bfsplit2(v.z, v.w, h1, l1);
                bHi[(2*kg  )*SSTR + o] = h0;
                bHi[(2*kg+1)*SSTR + o] = h1;
                bLo[(2*kg  )*SSTR + o] = l0;
                bLo[(2*kg+1)*SSTR + o] = l1;
            }
        }
        __syncthreads();

        // ---- mma: 3 passes x 4 ksteps (k16) ----
        #pragma unroll
        for (int pass = 0; pass < 3; pass++) {
            const uint32_t* aB = (pass == 2) ? aLo : aHi;
            const uint32_t* bB = (pass == 1) ? bLo : bHi;
            #pragma unroll
            for (int ks = 0; ks < 4; ks++) {
                const int j0 = ks*8;
                uint32_t afr[4][4];
                #pragma unroll
                for (int mt = 0; mt < 4; mt++) {
                    int m0 = wr*64 + mt*16;
                    afr[mt][0] = aB[(j0+tig  )*SSTR + m0 + g    ];
                    afr[mt][1] = aB[(j0+tig  )*SSTR + m0 + g + 8];
                    afr[mt][2] = aB[(j0+tig+4)*SSTR + m0 + g    ];
                    afr[mt][3] = aB[(j0+tig+4)*SSTR + m0 + g + 8];
                }
                #pragma unroll
                for (int nt = 0; nt < 4; nt++) {
                    int n0 = wc*32 + nt*8;
                    uint32_t b0 = bB[(j0+tig  )*SSTR + n0 + g];
                    uint32_t b1 = bB[(j0+tig+4)*SSTR + n0 + g];
                    #pragma unroll
                    for (int mt = 0; mt < 4; mt++)
                        MMA_BF16(acc[mt][nt], afr[mt], b0, b1);
                }
            }
        }
        __syncthreads();   // mma done before next chunk restages (or T write)
    }

    // ---- Epilogue: acc -> T[pix][129] with bias ----
    #pragma unroll
    for (int mt = 0; mt < 4; mt++) {
        #pragma unroll
        for (int nt = 0; nt < 4; nt++) {
            int row0 = wr*64 + mt*16 + g;
            int col  = wc*32 + nt*8 + 2*tig;
            T[ row0   *129 + col    ] = acc[mt][nt][0] + sbias[col];
            T[ row0   *129 + col + 1] = acc[mt][nt][1] + sbias[col+1];
            T[(row0+8)*129 + col    ] = acc[mt][nt][2] + sbias[col];
            T[(row0+8)*129 + col + 1] = acc[mt][nt][3] + sbias[col+1];
        }
    }
    __syncthreads();

    // Warp-parallel softmax stats: 8 warps x 16 pixels
    #pragma unroll
    for (int i = 0; i < 16; i++) {
        int p = wid*16 + i;
        float v0 = (lane      < Dd) ? T[p*129 + lane]      : -3.4e38f;
        float v1 = (lane + 32 < Dd) ? T[p*129 + lane + 32] : -3.4e38f;
        float mx = fmaxf(v0, v1);
        #pragma unroll
        for (int o = 16; o; o >>= 1) mx = fmaxf(mx, __shfl_xor_sync(~0u, mx, o));
        float s = 0.0f;
        if (lane      < Dd) s += expf(v0 - mx);
        if (lane + 32 < Dd) s += expf(v1 - mx);
        #pragma unroll
        for (int o = 16; o; o >>= 1) s += __shfl_xor_sync(~0u, s, o);
        if (lane == 0) { pmax[p] = mx; pinv[p] = 1.0f / s; }
    }
    __syncthreads();

    for (int i = tid; i < TILE_M*Dd; i += 256) {
        int pix = i / Dd;
        int d   = i - pix*Dd;
        depth_out[(size_t)(p0 + pix)*Dd + d] =
            expf(T[pix*129 + d] - pmax[pix]) * pinv[pix];
    }
    for (int i = tid; i < TILE_M*COUT; i += 256) {
        int pix = i >> 6;
        int c   = i & 63;
        g_feat[(size_t)(p0 + pix)*COUT + c] = T[pix*129 + Dd + c];
    }
}

// ---------------------------------------------------------------------------
// Kernel 2: voxel projection + depth-weighted feature splat.
//  Phase A: one projection per lane, predicated depth LDG.
//  Compact: thread-per-x in-place squeeze (order-preserving).
//  Phase B: WARP per x (cnt warp-uniform) -> safe x4 unroll, MLP=4 LDG.64,
//           lane owns channel pair (2l, 2l+1).
// ---------------------------------------------------------------------------
#define XQ 32     // x values per block
#define SACCP 68  // sacc row stride (floats)

__global__ __launch_bounds__(256, 6)
void bev_kernel(const float* __restrict__ c2e,
                const float* __restrict__ Kin,
                const float* __restrict__ depth,
                float* __restrict__ bev) {
    __shared__ float2 sl[XQ*42];        // [x][s] (wgt, feat_off_as_float)
    __shared__ float  sacc[XQ*SACCP];   // [x][c]
    __shared__ int    scnt[XQ];
    __shared__ float  sbase[Nc][ZZ][3];
    __shared__ float  scol0[Nc][4];
    __shared__ float  sK[Nc][4];

    const int blk = blockIdx.x;
    const int xq  = blk & 3;
    const int y   = (blk >> 2) & 127;
    const int b   = blk >> 9;
    const int tid = threadIdx.x;
    const float py = y*0.8f - 51.2f;

    if (tid < Nc*ZZ) {
        int n = tid / ZZ, z = tid - n*ZZ;
        const float* m = c2e + (b*Nc + n)*16;   // cam2ego 4x4
        float pz = (float)z - 2.5f;
        #pragma unroll
        for (int i = 0; i < 3; i++) {
            float e1 = m[4+i], e2 = m[8+i];
            float e3 = -(m[i]*m[3] + e1*m[7] + e2*m[11]);
            sbase[n][z][i] = py*e1 + pz*e2 + e3;
        }
        if (z == 0) {
            scol0[n][0] = m[0]; scol0[n][1] = m[1]; scol0[n][2] = m[2];
            const float* k = Kin + (b*Nc + n)*9;
            sK[n][0] = k[0]; sK[n][1] = k[4]; sK[n][2] = k[2]; sK[n][3] = k[5];
        }
    }
    __syncthreads();

    // ---- Phase A: per-lane projections (42 samples x 32 x = 1344) ----
    #pragma unroll
    for (int r = 0; r < 6; r++) {
        int idx = tid + 256*r;
        if (idx < Nc*ZZ*XQ) {
            int x = idx & (XQ-1);
            int s = idx >> 5;          // 0..41 (warp-uniform)
            int n = s / ZZ;
            int z = s - n*ZZ;
            float px = (float)(xq*XQ + x)*0.8f - 51.2f;
            float camx = px*scol0[n][0] + sbase[n][z][0];
            float camy = px*scol0[n][1] + sbase[n][z][1];
            float camz = px*scol0[n][2] + sbase[n][z][2];
            float rz   = 1.0f / fmaxf(camz, 0.1f);
            float fu   = (sK[n][0]*(camx*rz) + sK[n][2]) * 0.0625f;
            float fv   = (sK[n][1]*(camy*rz) + sK[n][3]) * 0.0625f;
            int   db   = (int)(camz - 1.0f);   // trunc == numpy astype(int32)
            bool valid = (fu >= 0.0f) && (fu < (float)Wc) &&
                         (fv >= 0.0f) && (fv < (float)Hc) &&
                         (camz > 0.5f) && (db >= 0) && (db < Dd);
            float wgt = 0.0f;
            int   off = 0;
            if (valid) {
                int u = (int)fu;
                int v = (int)fv;
                int pp = (b*Nc + n)*HW + v*Wc + u;
                wgt = depth[(size_t)pp*Dd + db];
                off = pp*COUT;
            }
            sl[x*42 + s] = make_float2(wgt, __int_as_float(off));
        }
    }
    __syncthreads();

    // ---- Compaction: thread x squeezes row x in place (order-preserving) ----
    if (tid < XQ) {
        float2* row = &sl[tid*42];
        int c = 0;
        #pragma unroll 7
        for (int s = 0; s < 42; s++) {
            float2 e = row[s];
            if (e.x != 0.0f) row[c++] = e;
        }
        scnt[tid] = c;
    }
    __syncthreads();

    // ---- Phase B: warp per x, channel pair per lane, x4 unrolled ----
    const int warp = tid >> 5;
    const int lane = tid & 31;
    const float* fb = g_feat + 2*lane;

    #pragma unroll
    for (int it = 0; it < 4; it++) {
        const int x = warp*4 + it;
        const int cnt = scnt[x];               // warp-uniform
        const float2* row = &sl[x*42];
        uint64_t acc = 0;                      // packed {2l, 2l+1}
        int j = 0;
        for (; j + 4 <= cnt; j += 4) {
            float4 e0 = *(const float4*)(row + j);       // entries j, j+1
            float4 e1 = *(const float4*)(row + j + 2);   // entries j+2, j+3
            uint64_t f0 = *(const uint64_t*)(fb + __float_as_int(e0.y));
            uint64_t f1 = *(const uint64_t*)(fb + __float_as_int(e0.w));
            uint64_t f2 = *(const uint64_t*)(fb + __float_as_int(e1.y));
            uint64_t f3 = *(const uint64_t*)(fb + __float_as_int(e1.w));
            uint64_t p0, p1, p2, p3;
            PACK2S(p0, e0.x); PACK2S(p1, e0.z);
            PACK2S(p2, e1.x); PACK2S(p3, e1.z);
            FFMA2(acc, p0, f0);
            FFMA2(acc, p1, f1);
            FFMA2(acc, p2, f2);
            FFMA2(acc, p3, f3);
        }
        if (j + 2 <= cnt) {
            float4 e0 = *(const float4*)(row + j);
            uint64_t f0 = *(const uint64_t*)(fb + __float_as_int(e0.y));
            uint64_t f1 = *(const uint64_t*)(fb + __float_as_int(e0.w));
            uint64_t p0, p1;
            PACK2S(p0, e0.x); PACK2S(p1, e0.z);
            FFMA2(acc, p0, f0);
            FFMA2(acc, p1, f1);
            j += 2;
        }
        if (j < cnt) {
            float2 e = row[j];
            uint64_t f = *(const uint64_t*)(fb + __float_as_int(e.y));
            uint64_t pw;
            PACK2S(pw, e.x);
            FFMA2(acc, pw, f);
        }
        float c0, c1;
        UNPACK2(c0, c1, acc);
        sacc[x*SACCP + 2*lane]     = c0;
        sacc[x*SACCP + 2*lane + 1] = c1;
    }
    __syncthreads();

    // bev[b, c, y, x] — 32-wide contiguous segments
    #pragma unroll
    for (int r = 0; r < 8; r++) {
        int i = tid + 256*r;
        int c = i >> 5;
        int x = i & 31;
        bev[(((size_t)b*COUT + c)*YY + y)*XX + xq*XQ + x] = sacc[x*SACCP + c];
    }
}

// ---------------------------------------------------------------------------
extern "C" void kernel_launch(void* const* d_in, const int* in_sizes, int n_in,
                              void* d_out, int out_size) {
    const float* img  = (const float*)d_in[0];  // (4,6,256,16,44)
    const float* c2e  = (const float*)d_in[1];  // (4,6,4,4)
    const float* Kin  = (const float*)d_in[2];  // (4,6,3,3)
    const float* w    = (const float*)d_in[3];  // (123,256)
    const float* bias = (const float*)d_in[4];  // (123,)
    float* out       = (float*)d_out;
    float* depth_out = out + BEV_SIZE;          // outputs: [bev | depth]

    const int smem_bytes = 4*TWORDS*4;          // 69632 B
    cudaFuncSetAttribute(gemm_mma, cudaFuncAttributeMaxDynamicSharedMemorySize, smem_bytes);

    gemm_mma<<<NPIX/TILE_M, 256, smem_bytes>>>(img, w, bias, depth_out);
    bev_kernel<<<Bc*YY*4, 256>>>(c2e, Kin, depth_out, out);
}